// round 13
// baseline (speedup 1.0000x reference)
#include <cuda_runtime.h>
#include <cuda_fp16.h>
#include <cstdint>
#include <cstddef>

#define T_STEPS 512
#define B_SZ    256
#define H_SZ    512
#define I_SZ    192
#define G4      2048   // 4*H
#define MT      131072 // B*T

// ---------------------------------------------------------------------------
// Scratch (allocation-free rule: __device__ globals)
// ---------------------------------------------------------------------------
__device__ float    g_xg[(size_t)T_STEPS * B_SZ * G4];  // [T][B][4H] fp32
__device__ __half   g_hhi[2][B_SZ * H_SZ];              // h hi (fp16), double-buffered
__device__ __half   g_hlo[2][B_SZ * H_SZ];              // h lo (fp16)
__device__ __half   g_wh [(size_t)G4 * H_SZ];           // fp16(W_hh)
__device__ __half   g_xhi[(size_t)MT * I_SZ];           // x hi (fp16)
__device__ __half   g_xlo[(size_t)MT * I_SZ];           // x lo (fp16)
__device__ __half   g_wih[(size_t)G4 * I_SZ];           // fp16(W_ih)
__device__ unsigned g_step[4][256];                     // per-producer flags [by][jt*8]

// ---------------------------------------------------------------------------
// Helpers (sm_80+ baseline instructions only — no 'a'-features)
// ---------------------------------------------------------------------------
__device__ __forceinline__ uint32_t smem_u32(const void* p) {
    uint32_t a;
    asm("{ .reg .u64 t; cvta.to.shared.u64 t, %1; cvt.u32.u64 %0, t; }" : "=r"(a) : "l"(p));
    return a;
}
__device__ __forceinline__ void ldsm_x4(uint32_t r[4], uint32_t addr) {
    asm volatile("ldmatrix.sync.aligned.m8n8.x4.shared.b16 {%0,%1,%2,%3}, [%4];"
                 : "=r"(r[0]), "=r"(r[1]), "=r"(r[2]), "=r"(r[3]) : "r"(addr));
}
__device__ __forceinline__ void ldsm_x2(uint32_t r[2], uint32_t addr) {
    asm volatile("ldmatrix.sync.aligned.m8n8.x2.shared.b16 {%0,%1}, [%2];"
                 : "=r"(r[0]), "=r"(r[1]) : "r"(addr));
}
__device__ __forceinline__ void mma16816(float c[4], const uint32_t a[4], const uint32_t b[2]) {
    asm volatile("mma.sync.aligned.m16n8k16.row.col.f32.f16.f16.f32 "
                 "{%0,%1,%2,%3}, {%4,%5,%6,%7}, {%8,%9}, {%0,%1,%2,%3};"
                 : "+f"(c[0]), "+f"(c[1]), "+f"(c[2]), "+f"(c[3])
                 : "r"(a[0]), "r"(a[1]), "r"(a[2]), "r"(a[3]), "r"(b[0]), "r"(b[1]));
}
#define CP_ASYNC16(saddr, gptr) \
    asm volatile("cp.async.cg.shared.global [%0], [%1], 16;" \
                 :: "r"(saddr), "l"((const void*)(gptr)))
#define CP_COMMIT() asm volatile("cp.async.commit_group;" ::: "memory")

__device__ __forceinline__ unsigned ld_acq(const unsigned* p) {
    unsigned v;
    asm volatile("ld.acquire.gpu.u32 %0, [%1];" : "=r"(v) : "l"(p) : "memory");
    return v;
}

__device__ __forceinline__ float fsigmoid(float x) {
    return __fdividef(1.0f, 1.0f + __expf(-x));
}
__device__ __forceinline__ float ftanh_fast(float x) {
    return 1.0f - __fdividef(2.0f, 1.0f + __expf(2.0f * x));
}

// ---------------------------------------------------------------------------
// Kernel 0: seed output with bias + reset producer flags
// ---------------------------------------------------------------------------
__global__ void init_out_kernel(float* __restrict__ out, const float* __restrict__ b_out) {
    int i = blockIdx.x * blockDim.x + threadIdx.x;
    if (i < 1024) ((unsigned*)g_step)[i] = 0u;
    if (i < B_SZ * T_STEPS) out[i] = b_out[0];
}

// ---------------------------------------------------------------------------
// Split / convert kernels
// ---------------------------------------------------------------------------
__global__ void conv_w_kernel(const float* __restrict__ W) {
    int i = blockIdx.x * blockDim.x + threadIdx.x;
    if (i < G4 * H_SZ) g_wh[i] = __float2half(W[i]);
}
__global__ void conv_wih_kernel(const float* __restrict__ W) {
    int i = blockIdx.x * blockDim.x + threadIdx.x;
    if (i < G4 * I_SZ) g_wih[i] = __float2half(W[i]);
}
__global__ void split_h0_kernel(const float* __restrict__ h0) {
    int i = blockIdx.x * blockDim.x + threadIdx.x;
    if (i < B_SZ * H_SZ) {
        float h = h0[i];
        __half hi = __float2half(h);
        g_hhi[1][i] = hi;   // t=0 reads buffer (0+1)&1 = 1
        g_hlo[1][i] = __float2half(h - __half2float(hi));
    }
}
__global__ void split_x_kernel(const float* __restrict__ obs, const float* __restrict__ act) {
    size_t i = (size_t)blockIdx.x * blockDim.x + threadIdx.x;
    if (i >= (size_t)MT * I_SZ) return;
    int m = (int)(i / I_SZ), k = (int)(i % I_SZ);
    int b = m >> 9, t = m & 511;
    float v = (k < 128) ? obs[((size_t)(b * T_STEPS + t)) * 128 + k]
                        : act[((size_t)(b * T_STEPS + t)) * 64 + (k - 128)];
    __half hi = __float2half(v);
    g_xhi[i] = hi;
    g_xlo[i] = __float2half(v - __half2float(hi));
}

// ---------------------------------------------------------------------------
// Kernel 1: xg GEMM, 2-term fp16 split HMMA (verified R12). Tile 64x64, K=192.
// ---------------------------------------------------------------------------
struct __align__(16) TileSmem {
    union {
        struct {
            __half Ahi[4][64][24];   // [k16][m][16 valid + 8 pad]
            __half Alo[4][64][24];
            __half Bh [4][64][24];
        };
        float Cx[64][65];
    };
};

__global__ void __launch_bounds__(256)
xg_mma_kernel(const float* __restrict__ b_ih, const float* __restrict__ b_hh) {
    __shared__ TileSmem sm;
    const int tid  = threadIdx.x;
    const int wid  = tid >> 5;
    const int lane = tid & 31;
    const int n0     = blockIdx.x * 64;
    const int m_base = blockIdx.y * 64;

    const int mw = wid >> 1;
    const int nw = wid & 1;
    const int m0 = mw * 16;
    const int a_row = m0 + (lane & 7) + 8 * ((lane >> 3) & 1);
    const int a_kh  = 8 * (lane >> 4);
    const int a_off = a_row * 24 + a_kh;
    const int b_lane = lane & 15;
    const int b_row0 = nw * 32 + (b_lane & 7);
    const int b_kh   = 8 * ((b_lane >> 3) & 1);

    const uint32_t sAhi = smem_u32(&sm.Ahi[0][0][0]);
    const uint32_t sAlo = smem_u32(&sm.Alo[0][0][0]);
    const uint32_t sBh  = smem_u32(&sm.Bh [0][0][0]);

    float c[4][4] = {};

    for (int kc = 0; kc < 3; kc++) {
        #pragma unroll
        for (int i = 0; i < 2; i++) {
            int flat = tid + i * 256;
            int row = flat >> 3, q = flat & 7;
            size_t ga = (size_t)(m_base + row) * I_SZ + kc * 64 + q * 8;
            uint4 va_hi = *reinterpret_cast<const uint4*>(g_xhi + ga);
            uint4 va_lo = *reinterpret_cast<const uint4*>(g_xlo + ga);
            *reinterpret_cast<uint4*>(&sm.Ahi[q >> 1][row][(q & 1) * 8]) = va_hi;
            *reinterpret_cast<uint4*>(&sm.Alo[q >> 1][row][(q & 1) * 8]) = va_lo;
            size_t gb = (size_t)(n0 + row) * I_SZ + kc * 64 + q * 8;
            uint4 vb = *reinterpret_cast<const uint4*>(g_wih + gb);
            *reinterpret_cast<uint4*>(&sm.Bh[q >> 1][row][(q & 1) * 8]) = vb;
        }
        __syncthreads();
        #pragma unroll
        for (int ks = 0; ks < 4; ks++) {
            const uint32_t plane = (uint32_t)ks * 3072;
            uint32_t ahi[4], alo[4];
            ldsm_x4(ahi, sAhi + plane + a_off * 2);
            ldsm_x4(alo, sAlo + plane + a_off * 2);
            #pragma unroll
            for (int g4 = 0; g4 < 4; g4++) {
                uint32_t bh[2];
                uint32_t boff = plane + ((b_row0 + g4 * 8) * 24 + b_kh) * 2;
                ldsm_x2(bh, sBh + boff);
                mma16816(c[g4], ahi, bh);
                mma16816(c[g4], alo, bh);
            }
        }
        __syncthreads();
    }

    {
        const int g  = lane >> 2;
        const int tq = lane & 3;
        #pragma unroll
        for (int g4 = 0; g4 < 4; g4++) {
            int n = nw * 32 + g4 * 8 + 2 * tq;
            sm.Cx[m0 + g][n]         = c[g4][0];
            sm.Cx[m0 + g][n + 1]     = c[g4][1];
            sm.Cx[m0 + g + 8][n]     = c[g4][2];
            sm.Cx[m0 + g + 8][n + 1] = c[g4][3];
        }
    }
    __syncthreads();

    const int m  = tid >> 2;
    const int cg = tid & 3;
    const int gm = m_base + m;
    const int b  = gm >> 9, tt = gm & 511;
    float* dst = g_xg + ((size_t)tt * B_SZ + b) * G4 + n0 + cg * 16;
    #pragma unroll
    for (int u4 = 0; u4 < 4; u4++) {
        float4 v;
        int nl = cg * 16 + u4 * 4;
        int n  = n0 + nl;
        v.x = sm.Cx[m][nl + 0] + b_ih[n + 0] + b_hh[n + 0];
        v.y = sm.Cx[m][nl + 1] + b_ih[n + 1] + b_hh[n + 1];
        v.z = sm.Cx[m][nl + 2] + b_ih[n + 2] + b_hh[n + 2];
        v.w = sm.Cx[m][nl + 3] + b_ih[n + 3] + b_hh[n + 3];
        *reinterpret_cast<float4*>(dst + u4 * 4) = v;
    }
}

// ---------------------------------------------------------------------------
// Kernel 2: PERSISTENT recurrence, fine-grained producer-flag sync.
// Grid (32, 4) = 128 blocks, 256 thr. fp16(W_hh) resident (64 KB smem).
// h = exact fp16 hi/lo split; 2 MMA terms. 4-stage cp.async, distance 2,
// 1 sync per chunk (R12-proven pattern). NO group barrier: each thread
// acquire-spins on the single producer flag its cp.async slice depends on.
// WAR across the h double-buffer is covered transitively: a block reaches its
// step-t epilogue only after consuming all 8 chunks (all 32 flags >= t), which
// certifies every peer finished its step-(t-1) reads. Drift bound: 1 step.
// Cell state c lives in REGISTERS (no global round-trip).
// Dynamic smem: [0,64K) W | [64K,+96K) A stages 0..3. Cx aliases stage 0.
// ---------------------------------------------------------------------------
#define W_BYTES      65536
#define ASTAGE_OFF   65536
#define ASTAGE_BYTES 24576
#define SMEM_TOTAL_P (ASTAGE_OFF + 4 * ASTAGE_BYTES)

__global__ void __launch_bounds__(256, 1)
lstm_persist_kernel(const float* __restrict__ c0,
                    const float* __restrict__ W_out,
                    float* __restrict__ out) {
    extern __shared__ uint8_t dynsmem[];
    const uint32_t dyn = smem_u32(dynsmem);
    const int tid  = threadIdx.x;
    const int wid  = tid >> 5;
    const int lane = tid & 31;
    const int jt     = blockIdx.x;
    const int j0     = jt * 16;
    const int by     = blockIdx.y;
    const int m_base = by * 64;

    // ---- load resident fp16 W (once): 4096 16B-chunks ----
    for (int idx = tid; idx < 4096; idx += 256) {
        int k16 = idx >> 7;
        int rem = idx & 127;
        int row = rem >> 1;
        int half = rem & 1;
        int gate = row >> 4, jj = row & 15;
        size_t g = (size_t)(gate * H_SZ + j0 + jj) * H_SZ + k16 * 16 + half * 8;
        uint32_t off = (uint32_t)(k16 * 2048 +
                       ((row * 32 + half * 16) ^ (((row >> 2) & 1) << 4)));
        *reinterpret_cast<uint4*>(dynsmem + off) =
            *reinterpret_cast<const uint4*>(g_wh + g);
    }
    __syncthreads();

    // ---- per-lane constants ----
    const int mw = wid >> 1;
    const int nw = wid & 1;
    const int m0 = mw * 16;
    const int a_row = m0 + (lane & 7) + 8 * ((lane >> 3) & 1);
    const int a_kh  = 8 * (lane >> 4);
    const uint32_t a_off2 = (uint32_t)(a_row * 24 + a_kh) * 2;
    const int b_lane = lane & 15;
    const int b_row0 = nw * 32 + (b_lane & 7);
    const uint32_t hb2 = (uint32_t)((16 * ((b_lane >> 3) & 1)) ^
                                    (((b_row0 >> 2) & 1) << 4));
    const uint32_t wB = dyn + (uint32_t)(b_row0 * 32) + hb2;

    // A-transfer coords: rows (tid>>3) and (tid>>3)+32, same q = tid&7.
    const int arow0 = tid >> 3;
    const int q     = tid & 7;
    const uint32_t soff = (uint32_t)((q >> 1) * 3072 + arow0 * 48 + (q & 1) * 16);
    // producer sub-index within a chunk for this thread's slice
    const int psub = q >> 1;   // 0..3

    const int em = tid >> 2;
    const int jg = tid & 3;
    const int eb = m_base + em;
    float (*Cx)[65] = reinterpret_cast<float (*)[65]>(dynsmem + ASTAGE_OFF);

    const int c0rot = (jt >> 2) & 7;   // chunk rotation: start at own region

    // cell state in registers
    float creg[4];
    #pragma unroll
    for (int u = 0; u < 4; u++)
        creg[u] = c0[(size_t)eb * H_SZ + j0 + jg * 4 + u];

    // prologue: prefetch xg for t=0
    float xg_r[4][4];
    {
        const float* xg_t = g_xg + (size_t)eb * G4;
        #pragma unroll
        for (int g = 0; g < 4; g++)
            *reinterpret_cast<float4*>(xg_r[g]) =
                *reinterpret_cast<const float4*>(xg_t + g * H_SZ + j0 + jg * 4);
    }

    for (int t = 0; t < T_STEPS; t++) {
        const __half* hhi = g_hhi[(t + 1) & 1];
        const __half* hlo = g_hlo[(t + 1) & 1];
        const int cb = t & 1;

        // issue logical chunk i (physical kc = rotated); spins on the ONE
        // producer flag this thread's slice depends on.
        auto issue_chunk = [&](int i) {
            const int kc = (c0rot + i) & 7;
            if (t > 0) {
                const unsigned* fl = &g_step[by][(4 * kc + psub) * 8];
                while (ld_acq(fl) < (unsigned)t) { }
            }
            const uint32_t sb = dyn + ASTAGE_OFF + (uint32_t)(i & 3) * ASTAGE_BYTES;
            #pragma unroll
            for (int r = 0; r < 2; r++) {
                const int row = arow0 + r * 32;
                const uint32_t so = soff + (uint32_t)r * (32 * 48);
                size_t ga = (size_t)(m_base + row) * H_SZ + kc * 64 + q * 8;
                CP_ASYNC16(sb + so,         hhi + ga);
                CP_ASYNC16(sb + 12288 + so, hlo + ga);
            }
            CP_COMMIT();
        };

        issue_chunk(0);
        issue_chunk(1);

        float c[4][4] = {};

        for (int i = 0; i < 8; i++) {
            if (i + 2 < 8) issue_chunk(i + 2);
            if (i < 6)       asm volatile("cp.async.wait_group 2;" ::: "memory");
            else if (i == 6) asm volatile("cp.async.wait_group 1;" ::: "memory");
            else             asm volatile("cp.async.wait_group 0;" ::: "memory");
            __syncthreads();   // single sync per chunk (4-stage safety, R12)

            const int kc = (c0rot + i) & 7;
            const uint32_t sb = dyn + ASTAGE_OFF + (uint32_t)(i & 3) * ASTAGE_BYTES;
            #pragma unroll
            for (int ks = 0; ks < 4; ks++) {
                const uint32_t aplane = sb + (uint32_t)ks * 3072;
                const uint32_t wplane = (uint32_t)(kc * 4 + ks) * 2048;
                uint32_t ahi[4], alo[4];
                ldsm_x4(ahi, aplane + a_off2);
                ldsm_x4(alo, aplane + 12288 + a_off2);
                #pragma unroll
                for (int g4 = 0; g4 < 4; g4++) {
                    uint32_t bh[2];
                    ldsm_x2(bh, wB + wplane + (uint32_t)(g4 * 256));
                    mma16816(c[g4], ahi, bh);
                    mma16816(c[g4], alo, bh);
                }
            }
        }
        // (post-loop sync removed: Cx = stage-0 bytes, whose last reads at
        //  logical chunk 4 are ordered by the top-of-chunk-5 barrier.)

        {
            const int g  = lane >> 2;
            const int tq = lane & 3;
            #pragma unroll
            for (int g4 = 0; g4 < 4; g4++) {
                int n = nw * 32 + g4 * 8 + 2 * tq;
                Cx[m0 + g][n]         = c[g4][0];
                Cx[m0 + g][n + 1]     = c[g4][1];
                Cx[m0 + g + 8][n]     = c[g4][2];
                Cx[m0 + g + 8][n + 1] = c[g4][3];
            }
        }
        __syncthreads();

        // ---- epilogue: thread owns (em, 4 j's); c in registers ----
        float s = 0.f;
        uint32_t hi_pack[2], lo_pack[2];
        #pragma unroll
        for (int u = 0; u < 4; u++) {
            const int jj = jg * 4 + u;
            const int j  = j0 + jj;
            float gi = Cx[em][0 * 16 + jj] + xg_r[0][u];
            float gf = Cx[em][1 * 16 + jj] + xg_r[1][u];
            float gg = Cx[em][2 * 16 + jj] + xg_r[2][u];
            float go = Cx[em][3 * 16 + jj] + xg_r[3][u];
            gi = fsigmoid(gi);
            gf = fsigmoid(gf);
            gg = ftanh_fast(gg);
            go = fsigmoid(go);
            float cn = gf * creg[u] + gi * gg;
            creg[u] = cn;
            float hv = go * ftanh_fast(cn);
            s += hv * W_out[j];
            __half hvi = __float2half(hv);
            __half hvl = __float2half(hv - __half2float(hvi));
            uint32_t uhi = (uint32_t)__half_as_ushort(hvi);
            uint32_t ulo = (uint32_t)__half_as_ushort(hvl);
            if (u & 1) { hi_pack[u >> 1] |= uhi << 16; lo_pack[u >> 1] |= ulo << 16; }
            else       { hi_pack[u >> 1]  = uhi;       lo_pack[u >> 1]  = ulo; }
        }
        size_t ho = (size_t)eb * H_SZ + j0 + jg * 4;
        *reinterpret_cast<uint2*>(&g_hhi[cb][ho]) = make_uint2(hi_pack[0], hi_pack[1]);
        *reinterpret_cast<uint2*>(&g_hlo[cb][ho]) = make_uint2(lo_pack[0], lo_pack[1]);

        // ---- publish h(t): fence (all threads) -> sync -> flag store ----
        __threadfence();
        __syncthreads();
        if (tid == 0)
            *(volatile unsigned*)&g_step[by][jt * 8] = (unsigned)(t + 1);

        // off the critical path: fused out projection + next-xg prefetch
        s += __shfl_xor_sync(0xffffffffu, s, 1);
        s += __shfl_xor_sync(0xffffffffu, s, 2);
        if (jg == 0) atomicAdd(&out[(size_t)eb * T_STEPS + t], s);
        if (t + 1 < T_STEPS) {
            const float* xg_t = g_xg + (size_t)(t + 1) * B_SZ * G4 + (size_t)eb * G4;
            #pragma unroll
            for (int g = 0; g < 4; g++)
                *reinterpret_cast<float4*>(xg_r[g]) =
                    *reinterpret_cast<const float4*>(xg_t + g * H_SZ + j0 + jg * 4);
        }
    }
}

// ---------------------------------------------------------------------------
extern "C" void kernel_launch(void* const* d_in, const int* in_sizes, int n_in,
                              void* d_out, int out_size) {
    const float* obs   = (const float*)d_in[0];
    const float* act   = (const float*)d_in[1];
    const float* h0    = (const float*)d_in[2];
    const float* c0    = (const float*)d_in[3];
    const float* W_ih  = (const float*)d_in[4];
    const float* W_hh  = (const float*)d_in[5];
    const float* b_ih  = (const float*)d_in[6];
    const float* b_hh  = (const float*)d_in[7];
    const float* W_out = (const float*)d_in[8];
    const float* b_out = (const float*)d_in[9];
    float* out = (float*)d_out;

    cudaFuncSetAttribute(lstm_persist_kernel,
                         cudaFuncAttributeMaxDynamicSharedMemorySize, SMEM_TOTAL_P);

    init_out_kernel<<<(B_SZ * T_STEPS + 255) / 256, 256>>>(out, b_out);
    conv_w_kernel<<<(G4 * H_SZ + 255) / 256, 256>>>(W_hh);
    conv_wih_kernel<<<(G4 * I_SZ + 255) / 256, 256>>>(W_ih);
    split_h0_kernel<<<(B_SZ * H_SZ + 255) / 256, 256>>>(h0);
    split_x_kernel<<<(int)(((size_t)MT * I_SZ + 255) / 256), 256>>>(obs, act);

    dim3 gxg(G4 / 64, MT / 64);
    xg_mma_kernel<<<gxg, 256>>>(b_ih, b_hh);

    dim3 gp(32, 4);
    lstm_persist_kernel<<<gp, 256, SMEM_TOTAL_P>>>(c0, W_out, out);
}

// round 14
// speedup vs baseline: 1.3531x; 1.3531x over previous
#include <cuda_runtime.h>
#include <cuda_fp16.h>
#include <cstdint>
#include <cstddef>

#define T_STEPS 512
#define B_SZ    256
#define H_SZ    512
#define I_SZ    192
#define G4      2048   // 4*H
#define MT      131072 // B*T
#define GROUP_BLOCKS 32

// ---------------------------------------------------------------------------
// Scratch (allocation-free rule: __device__ globals)
// ---------------------------------------------------------------------------
__device__ float    g_xg[(size_t)T_STEPS * B_SZ * G4];  // [T][B][4H] fp32
__device__ __half   g_hh[2][B_SZ * H_SZ];               // h (fp16), double-buffered
__device__ __half   g_wh [(size_t)G4 * H_SZ];           // fp16(W_hh)
__device__ __half   g_xhi[(size_t)MT * I_SZ];           // x hi (fp16)
__device__ __half   g_xlo[(size_t)MT * I_SZ];           // x lo (fp16)
__device__ __half   g_wih[(size_t)G4 * I_SZ];           // fp16(W_ih)
__device__ unsigned g_bars[4][32];                      // per-batch-tile barriers

// ---------------------------------------------------------------------------
// Helpers (sm_80+ baseline instructions only — no 'a'-features)
// ---------------------------------------------------------------------------
__device__ __forceinline__ uint32_t smem_u32(const void* p) {
    uint32_t a;
    asm("{ .reg .u64 t; cvta.to.shared.u64 t, %1; cvt.u32.u64 %0, t; }" : "=r"(a) : "l"(p));
    return a;
}
__device__ __forceinline__ void ldsm_x4(uint32_t r[4], uint32_t addr) {
    asm volatile("ldmatrix.sync.aligned.m8n8.x4.shared.b16 {%0,%1,%2,%3}, [%4];"
                 : "=r"(r[0]), "=r"(r[1]), "=r"(r[2]), "=r"(r[3]) : "r"(addr));
}
__device__ __forceinline__ void ldsm_x2(uint32_t r[2], uint32_t addr) {
    asm volatile("ldmatrix.sync.aligned.m8n8.x2.shared.b16 {%0,%1}, [%2];"
                 : "=r"(r[0]), "=r"(r[1]) : "r"(addr));
}
__device__ __forceinline__ void mma16816(float c[4], const uint32_t a[4], const uint32_t b[2]) {
    asm volatile("mma.sync.aligned.m16n8k16.row.col.f32.f16.f16.f32 "
                 "{%0,%1,%2,%3}, {%4,%5,%6,%7}, {%8,%9}, {%0,%1,%2,%3};"
                 : "+f"(c[0]), "+f"(c[1]), "+f"(c[2]), "+f"(c[3])
                 : "r"(a[0]), "r"(a[1]), "r"(a[2]), "r"(a[3]), "r"(b[0]), "r"(b[1]));
}
#define CP_ASYNC16(saddr, gptr) \
    asm volatile("cp.async.cg.shared.global [%0], [%1], 16;" \
                 :: "r"(saddr), "l"((const void*)(gptr)))
#define CP_COMMIT() asm volatile("cp.async.commit_group;" ::: "memory")

__device__ __forceinline__ float fsigmoid(float x) {
    return __fdividef(1.0f, 1.0f + __expf(-x));
}
__device__ __forceinline__ float ftanh_fast(float x) {
    return 1.0f - __fdividef(2.0f, 1.0f + __expf(2.0f * x));
}

// ---------------------------------------------------------------------------
// Kernel 0: seed output with bias + reset group barriers
// ---------------------------------------------------------------------------
__global__ void init_out_kernel(float* __restrict__ out, const float* __restrict__ b_out) {
    int i = blockIdx.x * blockDim.x + threadIdx.x;
    if (i < 128) ((unsigned*)g_bars)[i] = 0u;
    if (i < B_SZ * T_STEPS) out[i] = b_out[0];
}

// ---------------------------------------------------------------------------
// Split / convert kernels
// ---------------------------------------------------------------------------
__global__ void conv_w_kernel(const float* __restrict__ W) {
    int i = blockIdx.x * blockDim.x + threadIdx.x;
    if (i < G4 * H_SZ) g_wh[i] = __float2half(W[i]);
}
__global__ void conv_wih_kernel(const float* __restrict__ W) {
    int i = blockIdx.x * blockDim.x + threadIdx.x;
    if (i < G4 * I_SZ) g_wih[i] = __float2half(W[i]);
}
__global__ void split_h0_kernel(const float* __restrict__ h0) {
    int i = blockIdx.x * blockDim.x + threadIdx.x;
    if (i < B_SZ * H_SZ)
        g_hh[1][i] = __float2half(h0[i]);   // t=0 reads buffer (0+1)&1 = 1
}
__global__ void split_x_kernel(const float* __restrict__ obs, const float* __restrict__ act) {
    size_t i = (size_t)blockIdx.x * blockDim.x + threadIdx.x;
    if (i >= (size_t)MT * I_SZ) return;
    int m = (int)(i / I_SZ), k = (int)(i % I_SZ);
    int b = m >> 9, t = m & 511;
    float v = (k < 128) ? obs[((size_t)(b * T_STEPS + t)) * 128 + k]
                        : act[((size_t)(b * T_STEPS + t)) * 64 + (k - 128)];
    __half hi = __float2half(v);
    g_xhi[i] = hi;
    g_xlo[i] = __float2half(v - __half2float(hi));
}

// ---------------------------------------------------------------------------
// Kernel 1: xg GEMM, 2-term fp16 split HMMA (verified R12). Tile 64x64, K=192.
// ---------------------------------------------------------------------------
struct __align__(16) TileSmem {
    union {
        struct {
            __half Ahi[4][64][24];   // [k16][m][16 valid + 8 pad]
            __half Alo[4][64][24];
            __half Bh [4][64][24];
        };
        float Cx[64][65];
    };
};

__global__ void __launch_bounds__(256)
xg_mma_kernel(const float* __restrict__ b_ih, const float* __restrict__ b_hh) {
    __shared__ TileSmem sm;
    const int tid  = threadIdx.x;
    const int wid  = tid >> 5;
    const int lane = tid & 31;
    const int n0     = blockIdx.x * 64;
    const int m_base = blockIdx.y * 64;

    const int mw = wid >> 1;
    const int nw = wid & 1;
    const int m0 = mw * 16;
    const int a_row = m0 + (lane & 7) + 8 * ((lane >> 3) & 1);
    const int a_kh  = 8 * (lane >> 4);
    const int a_off = a_row * 24 + a_kh;
    const int b_lane = lane & 15;
    const int b_row0 = nw * 32 + (b_lane & 7);
    const int b_kh   = 8 * ((b_lane >> 3) & 1);

    const uint32_t sAhi = smem_u32(&sm.Ahi[0][0][0]);
    const uint32_t sAlo = smem_u32(&sm.Alo[0][0][0]);
    const uint32_t sBh  = smem_u32(&sm.Bh [0][0][0]);

    float c[4][4] = {};

    for (int kc = 0; kc < 3; kc++) {
        #pragma unroll
        for (int i = 0; i < 2; i++) {
            int flat = tid + i * 256;
            int row = flat >> 3, q = flat & 7;
            size_t ga = (size_t)(m_base + row) * I_SZ + kc * 64 + q * 8;
            uint4 va_hi = *reinterpret_cast<const uint4*>(g_xhi + ga);
            uint4 va_lo = *reinterpret_cast<const uint4*>(g_xlo + ga);
            *reinterpret_cast<uint4*>(&sm.Ahi[q >> 1][row][(q & 1) * 8]) = va_hi;
            *reinterpret_cast<uint4*>(&sm.Alo[q >> 1][row][(q & 1) * 8]) = va_lo;
            size_t gb = (size_t)(n0 + row) * I_SZ + kc * 64 + q * 8;
            uint4 vb = *reinterpret_cast<const uint4*>(g_wih + gb);
            *reinterpret_cast<uint4*>(&sm.Bh[q >> 1][row][(q & 1) * 8]) = vb;
        }
        __syncthreads();
        #pragma unroll
        for (int ks = 0; ks < 4; ks++) {
            const uint32_t plane = (uint32_t)ks * 3072;
            uint32_t ahi[4], alo[4];
            ldsm_x4(ahi, sAhi + plane + a_off * 2);
            ldsm_x4(alo, sAlo + plane + a_off * 2);
            #pragma unroll
            for (int g4 = 0; g4 < 4; g4++) {
                uint32_t bh[2];
                uint32_t boff = plane + ((b_row0 + g4 * 8) * 24 + b_kh) * 2;
                ldsm_x2(bh, sBh + boff);
                mma16816(c[g4], ahi, bh);
                mma16816(c[g4], alo, bh);
            }
        }
        __syncthreads();
    }

    {
        const int g  = lane >> 2;
        const int tq = lane & 3;
        #pragma unroll
        for (int g4 = 0; g4 < 4; g4++) {
            int n = nw * 32 + g4 * 8 + 2 * tq;
            sm.Cx[m0 + g][n]         = c[g4][0];
            sm.Cx[m0 + g][n + 1]     = c[g4][1];
            sm.Cx[m0 + g + 8][n]     = c[g4][2];
            sm.Cx[m0 + g + 8][n + 1] = c[g4][3];
        }
    }
    __syncthreads();

    const int m  = tid >> 2;
    const int cg = tid & 3;
    const int gm = m_base + m;
    const int b  = gm >> 9, tt = gm & 511;
    float* dst = g_xg + ((size_t)tt * B_SZ + b) * G4 + n0 + cg * 16;
    #pragma unroll
    for (int u4 = 0; u4 < 4; u4++) {
        float4 v;
        int nl = cg * 16 + u4 * 4;
        int n  = n0 + nl;
        v.x = sm.Cx[m][nl + 0] + b_ih[n + 0] + b_hh[n + 0];
        v.y = sm.Cx[m][nl + 1] + b_ih[n + 1] + b_hh[n + 1];
        v.z = sm.Cx[m][nl + 2] + b_ih[n + 2] + b_hh[n + 2];
        v.w = sm.Cx[m][nl + 3] + b_ih[n + 3] + b_hh[n + 3];
        *reinterpret_cast<float4*>(dst + u4 * 4) = v;
    }
}

// ---------------------------------------------------------------------------
// Kernel 2: PERSISTENT recurrence. Grid (32, 4) = 128 blocks, 256 thr.
// fp16(W_hh) resident (64 KB smem, pitch-32B rows, XOR-bit4/4-row swizzle).
// h = plain fp16 (1-term GEMM). K=512 in FOUR chunks of 128; 4 stages of
// 24 KB — a stage is never reused within a step (reuse hazard eliminated),
// and cross-step reuse is ordered by the epilogue/barrier syncs.
// 1 __syncthreads per chunk; R12-proven group barrier (32 blocks / batch tile).
// Cell state in registers. Dynamic smem: [0,64K) W | [64K,+96K) A stages.
// Cx (64x65 f32) aliases stage 0.
// ---------------------------------------------------------------------------
#define W_BYTES      65536
#define ASTAGE_OFF   65536
#define ASTAGE_BYTES 24576
#define SMEM_TOTAL_P (ASTAGE_OFF + 4 * ASTAGE_BYTES)

__global__ void __launch_bounds__(256, 1)
lstm_persist_kernel(const float* __restrict__ c0,
                    const float* __restrict__ W_out,
                    float* __restrict__ out) {
    extern __shared__ uint8_t dynsmem[];
    const uint32_t dyn = smem_u32(dynsmem);
    const int tid  = threadIdx.x;
    const int wid  = tid >> 5;
    const int lane = tid & 31;
    const int j0     = blockIdx.x * 16;
    const int by     = blockIdx.y;
    const int m_base = by * 64;

    // ---- load resident fp16 W (once): 4096 16B-chunks ----
    for (int idx = tid; idx < 4096; idx += 256) {
        int k16 = idx >> 7;
        int rem = idx & 127;
        int row = rem >> 1;
        int half = rem & 1;
        int gate = row >> 4, jj = row & 15;
        size_t g = (size_t)(gate * H_SZ + j0 + jj) * H_SZ + k16 * 16 + half * 8;
        uint32_t off = (uint32_t)(k16 * 2048 +
                       ((row * 32 + half * 16) ^ (((row >> 2) & 1) << 4)));
        *reinterpret_cast<uint4*>(dynsmem + off) =
            *reinterpret_cast<const uint4*>(g_wh + g);
    }
    __syncthreads();

    // ---- per-lane constants ----
    const int mw = wid >> 1;
    const int nw = wid & 1;
    const int m0 = mw * 16;
    const int a_row = m0 + (lane & 7) + 8 * ((lane >> 3) & 1);
    const int a_kh  = 8 * (lane >> 4);
    const uint32_t a_off2 = (uint32_t)(a_row * 24 + a_kh) * 2;
    const int b_lane = lane & 15;
    const int b_row0 = nw * 32 + (b_lane & 7);
    const uint32_t hb2 = (uint32_t)((16 * ((b_lane >> 3) & 1)) ^
                                    (((b_row0 >> 2) & 1) << 4));
    const uint32_t wB = dyn + (uint32_t)(b_row0 * 32) + hb2;

    const int em = tid >> 2;
    const int jg = tid & 3;
    const int eb = m_base + em;
    float (*Cx)[65] = reinterpret_cast<float (*)[65]>(dynsmem + ASTAGE_OFF);
    volatile unsigned* vbar = &g_bars[by][0];

    // cell state in registers
    float creg[4];
    #pragma unroll
    for (int u = 0; u < 4; u++)
        creg[u] = c0[(size_t)eb * H_SZ + j0 + jg * 4 + u];

    // prologue: prefetch xg for t=0
    float xg_r[4][4];
    {
        const float* xg_t = g_xg + (size_t)eb * G4;
        #pragma unroll
        for (int g = 0; g < 4; g++)
            *reinterpret_cast<float4*>(xg_r[g]) =
                *reinterpret_cast<const float4*>(xg_t + g * H_SZ + j0 + jg * 4);
    }

    for (int t = 0; t < T_STEPS; t++) {
        if (t > 0) {
            if (tid == 0) {
                const unsigned target = (unsigned)GROUP_BLOCKS * (unsigned)t;
                while (*vbar < target) { }
                __threadfence();
            }
            __syncthreads();
        }

        const __half* hh = g_hh[(t + 1) & 1];
        const int cb = t & 1;

        // chunk kc covers k = kc*128 .. +127; 1024 16B-transfers per chunk,
        // 4 per thread: flat = tid + j*256, row = flat>>4, q = flat&15.
        auto issue_chunk = [&](int kc) {
            const uint32_t sb = dyn + ASTAGE_OFF + (uint32_t)kc * ASTAGE_BYTES;
            #pragma unroll
            for (int j = 0; j < 4; j++) {
                const int flat = tid + j * 256;
                const int row = flat >> 4;
                const int q   = flat & 15;
                const uint32_t soff =
                    (uint32_t)((q >> 1) * 3072 + row * 48 + (q & 1) * 16);
                size_t ga = (size_t)(m_base + row) * H_SZ + kc * 128 + q * 8;
                CP_ASYNC16(sb + soff, hh + ga);
            }
            CP_COMMIT();
        };

        issue_chunk(0);
        issue_chunk(1);

        float c[4][4] = {};

        for (int kc = 0; kc < 4; kc++) {
            if (kc + 2 < 4) issue_chunk(kc + 2);
            if (kc < 2)       asm volatile("cp.async.wait_group 2;" ::: "memory");
            else if (kc == 2) asm volatile("cp.async.wait_group 1;" ::: "memory");
            else              asm volatile("cp.async.wait_group 0;" ::: "memory");
            __syncthreads();   // single sync per chunk; stages never reused in-step

            const uint32_t sb = dyn + ASTAGE_OFF + (uint32_t)kc * ASTAGE_BYTES;
            #pragma unroll
            for (int ks = 0; ks < 8; ks++) {
                const uint32_t aplane = sb + (uint32_t)ks * 3072;
                const uint32_t wplane = (uint32_t)(kc * 8 + ks) * 2048;
                uint32_t ahi[4];
                ldsm_x4(ahi, aplane + a_off2);
                #pragma unroll
                for (int g4 = 0; g4 < 4; g4++) {
                    uint32_t bh[2];
                    ldsm_x2(bh, wB + wplane + (uint32_t)(g4 * 256));
                    mma16816(c[g4], ahi, bh);
                }
            }
        }
        __syncthreads();  // stage-0 MMA reads (kc=0) done before Cx overwrite

        {
            const int g  = lane >> 2;
            const int tq = lane & 3;
            #pragma unroll
            for (int g4 = 0; g4 < 4; g4++) {
                int n = nw * 32 + g4 * 8 + 2 * tq;
                Cx[m0 + g][n]         = c[g4][0];
                Cx[m0 + g][n + 1]     = c[g4][1];
                Cx[m0 + g + 8][n]     = c[g4][2];
                Cx[m0 + g + 8][n + 1] = c[g4][3];
            }
        }
        __syncthreads();

        // ---- epilogue: thread owns (em, 4 j's); c in registers ----
        float s = 0.f;
        uint32_t h_pack[2];
        #pragma unroll
        for (int u = 0; u < 4; u++) {
            const int jj = jg * 4 + u;
            const int j  = j0 + jj;
            float gi = Cx[em][0 * 16 + jj] + xg_r[0][u];
            float gf = Cx[em][1 * 16 + jj] + xg_r[1][u];
            float gg = Cx[em][2 * 16 + jj] + xg_r[2][u];
            float go = Cx[em][3 * 16 + jj] + xg_r[3][u];
            gi = fsigmoid(gi);
            gf = fsigmoid(gf);
            gg = ftanh_fast(gg);
            go = fsigmoid(go);
            float cn = gf * creg[u] + gi * gg;
            creg[u] = cn;
            float hv = go * ftanh_fast(cn);
            s += hv * W_out[j];
            uint32_t uh = (uint32_t)__half_as_ushort(__float2half(hv));
            if (u & 1) h_pack[u >> 1] |= uh << 16;
            else       h_pack[u >> 1]  = uh;
        }
        size_t ho = (size_t)eb * H_SZ + j0 + jg * 4;
        *reinterpret_cast<uint2*>(&g_hh[cb][ho]) = make_uint2(h_pack[0], h_pack[1]);

        s += __shfl_xor_sync(0xffffffffu, s, 1);
        s += __shfl_xor_sync(0xffffffffu, s, 2);
        if (jg == 0) atomicAdd(&out[(size_t)eb * T_STEPS + t], s);

        // ---- arrive (release), then prefetch next xg during peers' arrival ----
        __threadfence();
        __syncthreads();
        if (tid == 0) atomicAdd(&g_bars[by][0], 1u);
        if (t + 1 < T_STEPS) {
            const float* xg_t = g_xg + (size_t)(t + 1) * B_SZ * G4 + (size_t)eb * G4;
            #pragma unroll
            for (int g = 0; g < 4; g++)
                *reinterpret_cast<float4*>(xg_r[g]) =
                    *reinterpret_cast<const float4*>(xg_t + g * H_SZ + j0 + jg * 4);
        }
    }
}

// ---------------------------------------------------------------------------
extern "C" void kernel_launch(void* const* d_in, const int* in_sizes, int n_in,
                              void* d_out, int out_size) {
    const float* obs   = (const float*)d_in[0];
    const float* act   = (const float*)d_in[1];
    const float* h0    = (const float*)d_in[2];
    const float* c0    = (const float*)d_in[3];
    const float* W_ih  = (const float*)d_in[4];
    const float* W_hh  = (const float*)d_in[5];
    const float* b_ih  = (const float*)d_in[6];
    const float* b_hh  = (const float*)d_in[7];
    const float* W_out = (const float*)d_in[8];
    const float* b_out = (const float*)d_in[9];
    float* out = (float*)d_out;

    cudaFuncSetAttribute(lstm_persist_kernel,
                         cudaFuncAttributeMaxDynamicSharedMemorySize, SMEM_TOTAL_P);

    init_out_kernel<<<(B_SZ * T_STEPS + 255) / 256, 256>>>(out, b_out);
    conv_w_kernel<<<(G4 * H_SZ + 255) / 256, 256>>>(W_hh);
    conv_wih_kernel<<<(G4 * I_SZ + 255) / 256, 256>>>(W_ih);
    split_h0_kernel<<<(B_SZ * H_SZ + 255) / 256, 256>>>(h0);
    split_x_kernel<<<(int)(((size_t)MT * I_SZ + 255) / 256), 256>>>(obs, act);

    dim3 gxg(G4 / 64, MT / 64);
    xg_mma_kernel<<<gxg, 256>>>(b_ih, b_hh);

    dim3 gp(32, 4);
    lstm_persist_kernel<<<gp, 256, SMEM_TOTAL_P>>>(c0, W_out, out);
}

// round 15
// speedup vs baseline: 1.3737x; 1.0152x over previous
#include <cuda_runtime.h>
#include <cuda_fp16.h>
#include <cstdint>
#include <cstddef>

#define T_STEPS 512
#define B_SZ    256
#define H_SZ    512
#define I_SZ    192
#define G4      2048   // 4*H
#define MT      131072 // B*T
#define GROUP_BLOCKS 32

// ---------------------------------------------------------------------------
// Scratch (allocation-free rule: __device__ globals)
// ---------------------------------------------------------------------------
__device__ float    g_xg[(size_t)T_STEPS * B_SZ * G4];  // [T][B][4H] fp32
__device__ __half   g_hh[2][B_SZ * H_SZ];               // h (fp16), double-buffered
__device__ __half   g_wh [(size_t)G4 * H_SZ];           // fp16(W_hh)
__device__ __half   g_xhi[(size_t)MT * I_SZ];           // x hi (fp16)
__device__ __half   g_xlo[(size_t)MT * I_SZ];           // x lo (fp16)
__device__ __half   g_wih[(size_t)G4 * I_SZ];           // fp16(W_ih)
__device__ unsigned g_bars[4][32];                      // per-batch-tile barriers

// ---------------------------------------------------------------------------
// Helpers (sm_80+ baseline instructions only — no 'a'-features)
// ---------------------------------------------------------------------------
__device__ __forceinline__ uint32_t smem_u32(const void* p) {
    uint32_t a;
    asm("{ .reg .u64 t; cvta.to.shared.u64 t, %1; cvt.u32.u64 %0, t; }" : "=r"(a) : "l"(p));
    return a;
}
__device__ __forceinline__ void ldsm_x4(uint32_t r[4], uint32_t addr) {
    asm volatile("ldmatrix.sync.aligned.m8n8.x4.shared.b16 {%0,%1,%2,%3}, [%4];"
                 : "=r"(r[0]), "=r"(r[1]), "=r"(r[2]), "=r"(r[3]) : "r"(addr));
}
__device__ __forceinline__ void ldsm_x2(uint32_t r[2], uint32_t addr) {
    asm volatile("ldmatrix.sync.aligned.m8n8.x2.shared.b16 {%0,%1}, [%2];"
                 : "=r"(r[0]), "=r"(r[1]) : "r"(addr));
}
__device__ __forceinline__ void mma16816(float c[4], const uint32_t a[4], const uint32_t b[2]) {
    asm volatile("mma.sync.aligned.m16n8k16.row.col.f32.f16.f16.f32 "
                 "{%0,%1,%2,%3}, {%4,%5,%6,%7}, {%8,%9}, {%0,%1,%2,%3};"
                 : "+f"(c[0]), "+f"(c[1]), "+f"(c[2]), "+f"(c[3])
                 : "r"(a[0]), "r"(a[1]), "r"(a[2]), "r"(a[3]), "r"(b[0]), "r"(b[1]));
}
#define CP_ASYNC16(saddr, gptr) \
    asm volatile("cp.async.cg.shared.global [%0], [%1], 16;" \
                 :: "r"(saddr), "l"((const void*)(gptr)))
#define CP_COMMIT() asm volatile("cp.async.commit_group;" ::: "memory")

__device__ __forceinline__ float fsigmoid(float x) {
    return __fdividef(1.0f, 1.0f + __expf(-x));
}
__device__ __forceinline__ float ftanh_fast(float x) {
    return 1.0f - __fdividef(2.0f, 1.0f + __expf(2.0f * x));
}

// ---------------------------------------------------------------------------
// Kernel 0: seed output with bias + reset group barriers
// ---------------------------------------------------------------------------
__global__ void init_out_kernel(float* __restrict__ out, const float* __restrict__ b_out) {
    int i = blockIdx.x * blockDim.x + threadIdx.x;
    if (i < 128) ((unsigned*)g_bars)[i] = 0u;
    if (i < B_SZ * T_STEPS) out[i] = b_out[0];
}

// ---------------------------------------------------------------------------
// Split / convert kernels
// ---------------------------------------------------------------------------
__global__ void conv_w_kernel(const float* __restrict__ W) {
    int i = blockIdx.x * blockDim.x + threadIdx.x;
    if (i < G4 * H_SZ) g_wh[i] = __float2half(W[i]);
}
__global__ void conv_wih_kernel(const float* __restrict__ W) {
    int i = blockIdx.x * blockDim.x + threadIdx.x;
    if (i < G4 * I_SZ) g_wih[i] = __float2half(W[i]);
}
__global__ void split_h0_kernel(const float* __restrict__ h0) {
    int i = blockIdx.x * blockDim.x + threadIdx.x;
    if (i < B_SZ * H_SZ)
        g_hh[1][i] = __float2half(h0[i]);   // t=0 reads buffer (0+1)&1 = 1
}
__global__ void split_x_kernel(const float* __restrict__ obs, const float* __restrict__ act) {
    size_t i = (size_t)blockIdx.x * blockDim.x + threadIdx.x;
    if (i >= (size_t)MT * I_SZ) return;
    int m = (int)(i / I_SZ), k = (int)(i % I_SZ);
    int b = m >> 9, t = m & 511;
    float v = (k < 128) ? obs[((size_t)(b * T_STEPS + t)) * 128 + k]
                        : act[((size_t)(b * T_STEPS + t)) * 64 + (k - 128)];
    __half hi = __float2half(v);
    g_xhi[i] = hi;
    g_xlo[i] = __float2half(v - __half2float(hi));
}

// ---------------------------------------------------------------------------
// Kernel 1: xg GEMM, 2-term fp16 split HMMA (verified R12). Tile 64x64, K=192.
// ---------------------------------------------------------------------------
struct __align__(16) TileSmem {
    union {
        struct {
            __half Ahi[4][64][24];   // [k16][m][16 valid + 8 pad]
            __half Alo[4][64][24];
            __half Bh [4][64][24];
        };
        float Cx[64][65];
    };
};

__global__ void __launch_bounds__(256)
xg_mma_kernel(const float* __restrict__ b_ih, const float* __restrict__ b_hh) {
    __shared__ TileSmem sm;
    const int tid  = threadIdx.x;
    const int wid  = tid >> 5;
    const int lane = tid & 31;
    const int n0     = blockIdx.x * 64;
    const int m_base = blockIdx.y * 64;

    const int mw = wid >> 1;
    const int nw = wid & 1;
    const int m0 = mw * 16;
    const int a_row = m0 + (lane & 7) + 8 * ((lane >> 3) & 1);
    const int a_kh  = 8 * (lane >> 4);
    const int a_off = a_row * 24 + a_kh;
    const int b_lane = lane & 15;
    const int b_row0 = nw * 32 + (b_lane & 7);
    const int b_kh   = 8 * ((b_lane >> 3) & 1);

    const uint32_t sAhi = smem_u32(&sm.Ahi[0][0][0]);
    const uint32_t sAlo = smem_u32(&sm.Alo[0][0][0]);
    const uint32_t sBh  = smem_u32(&sm.Bh [0][0][0]);

    float c[4][4] = {};

    for (int kc = 0; kc < 3; kc++) {
        #pragma unroll
        for (int i = 0; i < 2; i++) {
            int flat = tid + i * 256;
            int row = flat >> 3, q = flat & 7;
            size_t ga = (size_t)(m_base + row) * I_SZ + kc * 64 + q * 8;
            uint4 va_hi = *reinterpret_cast<const uint4*>(g_xhi + ga);
            uint4 va_lo = *reinterpret_cast<const uint4*>(g_xlo + ga);
            *reinterpret_cast<uint4*>(&sm.Ahi[q >> 1][row][(q & 1) * 8]) = va_hi;
            *reinterpret_cast<uint4*>(&sm.Alo[q >> 1][row][(q & 1) * 8]) = va_lo;
            size_t gb = (size_t)(n0 + row) * I_SZ + kc * 64 + q * 8;
            uint4 vb = *reinterpret_cast<const uint4*>(g_wih + gb);
            *reinterpret_cast<uint4*>(&sm.Bh[q >> 1][row][(q & 1) * 8]) = vb;
        }
        __syncthreads();
        #pragma unroll
        for (int ks = 0; ks < 4; ks++) {
            const uint32_t plane = (uint32_t)ks * 3072;
            uint32_t ahi[4], alo[4];
            ldsm_x4(ahi, sAhi + plane + a_off * 2);
            ldsm_x4(alo, sAlo + plane + a_off * 2);
            #pragma unroll
            for (int g4 = 0; g4 < 4; g4++) {
                uint32_t bh[2];
                uint32_t boff = plane + ((b_row0 + g4 * 8) * 24 + b_kh) * 2;
                ldsm_x2(bh, sBh + boff);
                mma16816(c[g4], ahi, bh);
                mma16816(c[g4], alo, bh);
            }
        }
        __syncthreads();
    }

    {
        const int g  = lane >> 2;
        const int tq = lane & 3;
        #pragma unroll
        for (int g4 = 0; g4 < 4; g4++) {
            int n = nw * 32 + g4 * 8 + 2 * tq;
            sm.Cx[m0 + g][n]         = c[g4][0];
            sm.Cx[m0 + g][n + 1]     = c[g4][1];
            sm.Cx[m0 + g + 8][n]     = c[g4][2];
            sm.Cx[m0 + g + 8][n + 1] = c[g4][3];
        }
    }
    __syncthreads();

    const int m  = tid >> 2;
    const int cg = tid & 3;
    const int gm = m_base + m;
    const int b  = gm >> 9, tt = gm & 511;
    float* dst = g_xg + ((size_t)tt * B_SZ + b) * G4 + n0 + cg * 16;
    #pragma unroll
    for (int u4 = 0; u4 < 4; u4++) {
        float4 v;
        int nl = cg * 16 + u4 * 4;
        int n  = n0 + nl;
        v.x = sm.Cx[m][nl + 0] + b_ih[n + 0] + b_hh[n + 0];
        v.y = sm.Cx[m][nl + 1] + b_ih[n + 1] + b_hh[n + 1];
        v.z = sm.Cx[m][nl + 2] + b_ih[n + 2] + b_hh[n + 2];
        v.w = sm.Cx[m][nl + 3] + b_ih[n + 3] + b_hh[n + 3];
        *reinterpret_cast<float4*>(dst + u4 * 4) = v;
    }
}

// ---------------------------------------------------------------------------
// Kernel 2: PERSISTENT recurrence. Grid (32, 4) = 128 blocks, 256 thr.
// fp16(W_hh) resident (64 KB smem). h = plain fp16, 1-term GEMM.
// K=512 in TWO chunks of 256 (2 stages x 48 KB): both issued up-front (full
// MLP), chunk-1 load hides under chunk-0 compute; TWO chunk barriers/step.
// Post-MMA barrier removed: chunk-1 compute reads only stage-1 bytes; stage-0
// reads completed before every thread passed the chunk-1 barrier, so Cx
// (aliasing stage 0) can be written immediately after a thread's own MMAs.
// Cell state + W_out in registers. Group barrier (32 blocks/batch tile).
// Dynamic smem: [0,64K) W | [64K,64K+96K) stages. Cx aliases stage 0.
// ---------------------------------------------------------------------------
#define W_BYTES      65536
#define ASTAGE_OFF   65536
#define ASTAGE_BYTES 49152
#define SMEM_TOTAL_P (ASTAGE_OFF + 2 * ASTAGE_BYTES)

__global__ void __launch_bounds__(256, 1)
lstm_persist_kernel(const float* __restrict__ c0,
                    const float* __restrict__ W_out,
                    float* __restrict__ out) {
    extern __shared__ uint8_t dynsmem[];
    const uint32_t dyn = smem_u32(dynsmem);
    const int tid  = threadIdx.x;
    const int wid  = tid >> 5;
    const int lane = tid & 31;
    const int j0     = blockIdx.x * 16;
    const int by     = blockIdx.y;
    const int m_base = by * 64;

    // ---- load resident fp16 W (once): 4096 16B-chunks ----
    for (int idx = tid; idx < 4096; idx += 256) {
        int k16 = idx >> 7;
        int rem = idx & 127;
        int row = rem >> 1;
        int half = rem & 1;
        int gate = row >> 4, jj = row & 15;
        size_t g = (size_t)(gate * H_SZ + j0 + jj) * H_SZ + k16 * 16 + half * 8;
        uint32_t off = (uint32_t)(k16 * 2048 +
                       ((row * 32 + half * 16) ^ (((row >> 2) & 1) << 4)));
        *reinterpret_cast<uint4*>(dynsmem + off) =
            *reinterpret_cast<const uint4*>(g_wh + g);
    }
    __syncthreads();

    // ---- per-lane constants ----
    const int mw = wid >> 1;
    const int nw = wid & 1;
    const int m0 = mw * 16;
    const int a_row = m0 + (lane & 7) + 8 * ((lane >> 3) & 1);
    const int a_kh  = 8 * (lane >> 4);
    const uint32_t a_off2 = (uint32_t)(a_row * 24 + a_kh) * 2;
    const int b_lane = lane & 15;
    const int b_row0 = nw * 32 + (b_lane & 7);
    const uint32_t hb2 = (uint32_t)((16 * ((b_lane >> 3) & 1)) ^
                                    (((b_row0 >> 2) & 1) << 4));
    const uint32_t wB = dyn + (uint32_t)(b_row0 * 32) + hb2;

    const int em = tid >> 2;
    const int jg = tid & 3;
    const int eb = m_base + em;
    float (*Cx)[65] = reinterpret_cast<float (*)[65]>(dynsmem + ASTAGE_OFF);
    volatile unsigned* vbar = &g_bars[by][0];

    // cell state + W_out in registers
    float creg[4], wout_r[4];
    #pragma unroll
    for (int u = 0; u < 4; u++) {
        creg[u]   = c0[(size_t)eb * H_SZ + j0 + jg * 4 + u];
        wout_r[u] = W_out[j0 + jg * 4 + u];
    }

    // prologue: prefetch xg for t=0
    float xg_r[4][4];
    {
        const float* xg_t = g_xg + (size_t)eb * G4;
        #pragma unroll
        for (int g = 0; g < 4; g++)
            *reinterpret_cast<float4*>(xg_r[g]) =
                *reinterpret_cast<const float4*>(xg_t + g * H_SZ + j0 + jg * 4);
    }

    for (int t = 0; t < T_STEPS; t++) {
        if (t > 0) {
            if (tid == 0) {
                const unsigned target = (unsigned)GROUP_BLOCKS * (unsigned)t;
                while (*vbar < target) { }
                __threadfence();
            }
            __syncthreads();
        }

        const __half* hh = g_hh[(t + 1) & 1];
        const int cb = t & 1;

        // chunk kc covers k = kc*256 .. +255; 2048 16B transfers, 8/thread.
        auto issue_chunk = [&](int kc) {
            const uint32_t sb = dyn + ASTAGE_OFF + (uint32_t)kc * ASTAGE_BYTES;
            #pragma unroll
            for (int j = 0; j < 8; j++) {
                const int flat = tid + j * 256;
                const int row = flat >> 5;
                const int q   = flat & 31;
                const uint32_t soff =
                    (uint32_t)((q >> 1) * 3072 + row * 48 + (q & 1) * 16);
                size_t ga = (size_t)(m_base + row) * H_SZ + kc * 256 + q * 8;
                CP_ASYNC16(sb + soff, hh + ga);
            }
            CP_COMMIT();
        };

        issue_chunk(0);
        issue_chunk(1);

        float c[4][4] = {};

        #pragma unroll
        for (int kc = 0; kc < 2; kc++) {
            if (kc == 0) asm volatile("cp.async.wait_group 1;" ::: "memory");
            else         asm volatile("cp.async.wait_group 0;" ::: "memory");
            __syncthreads();

            const uint32_t sb = dyn + ASTAGE_OFF + (uint32_t)kc * ASTAGE_BYTES;
            #pragma unroll
            for (int ks = 0; ks < 16; ks++) {
                const uint32_t aplane = sb + (uint32_t)ks * 3072;
                const uint32_t wplane = (uint32_t)(kc * 16 + ks) * 2048;
                uint32_t ahi[4];
                ldsm_x4(ahi, aplane + a_off2);
                #pragma unroll
                for (int g4 = 0; g4 < 4; g4++) {
                    uint32_t bh[2];
                    ldsm_x2(bh, wB + wplane + (uint32_t)(g4 * 256));
                    mma16816(c[g4], ahi, bh);
                }
            }
        }

        // fragments -> Cx: NO barrier needed (chunk-1 compute reads stage-1
        // only; stage-0 reads done before all threads passed chunk-1 barrier)
        {
            const int g  = lane >> 2;
            const int tq = lane & 3;
            #pragma unroll
            for (int g4 = 0; g4 < 4; g4++) {
                int n = nw * 32 + g4 * 8 + 2 * tq;
                Cx[m0 + g][n]         = c[g4][0];
                Cx[m0 + g][n + 1]     = c[g4][1];
                Cx[m0 + g + 8][n]     = c[g4][2];
                Cx[m0 + g + 8][n + 1] = c[g4][3];
            }
        }
        __syncthreads();

        // ---- epilogue: thread owns (em, 4 j's); c, W_out in registers ----
        float s = 0.f;
        uint32_t h_pack[2];
        #pragma unroll
        for (int u = 0; u < 4; u++) {
            const int jj = jg * 4 + u;
            float gi = Cx[em][0 * 16 + jj] + xg_r[0][u];
            float gf = Cx[em][1 * 16 + jj] + xg_r[1][u];
            float gg = Cx[em][2 * 16 + jj] + xg_r[2][u];
            float go = Cx[em][3 * 16 + jj] + xg_r[3][u];
            gi = fsigmoid(gi);
            gf = fsigmoid(gf);
            gg = ftanh_fast(gg);
            go = fsigmoid(go);
            float cn = gf * creg[u] + gi * gg;
            creg[u] = cn;
            float hv = go * ftanh_fast(cn);
            s += hv * wout_r[u];
            uint32_t uh = (uint32_t)__half_as_ushort(__float2half(hv));
            if (u & 1) h_pack[u >> 1] |= uh << 16;
            else       h_pack[u >> 1]  = uh;
        }
        size_t ho = (size_t)eb * H_SZ + j0 + jg * 4;
        *reinterpret_cast<uint2*>(&g_hh[cb][ho]) = make_uint2(h_pack[0], h_pack[1]);

        s += __shfl_xor_sync(0xffffffffu, s, 1);
        s += __shfl_xor_sync(0xffffffffu, s, 2);
        if (jg == 0) atomicAdd(&out[(size_t)eb * T_STEPS + t], s);

        // ---- arrive (release), then prefetch next xg during peers' arrival ----
        __threadfence();
        __syncthreads();
        if (tid == 0) atomicAdd(&g_bars[by][0], 1u);
        if (t + 1 < T_STEPS) {
            const float* xg_t = g_xg + (size_t)(t + 1) * B_SZ * G4 + (size_t)eb * G4;
            #pragma unroll
            for (int g = 0; g < 4; g++)
                *reinterpret_cast<float4*>(xg_r[g]) =
                    *reinterpret_cast<const float4*>(xg_t + g * H_SZ + j0 + jg * 4);
        }
    }
}

// ---------------------------------------------------------------------------
extern "C" void kernel_launch(void* const* d_in, const int* in_sizes, int n_in,
                              void* d_out, int out_size) {
    const float* obs   = (const float*)d_in[0];
    const float* act   = (const float*)d_in[1];
    const float* h0    = (const float*)d_in[2];
    const float* c0    = (const float*)d_in[3];
    const float* W_ih  = (const float*)d_in[4];
    const float* W_hh  = (const float*)d_in[5];
    const float* b_ih  = (const float*)d_in[6];
    const float* b_hh  = (const float*)d_in[7];
    const float* W_out = (const float*)d_in[8];
    const float* b_out = (const float*)d_in[9];
    float* out = (float*)d_out;

    cudaFuncSetAttribute(lstm_persist_kernel,
                         cudaFuncAttributeMaxDynamicSharedMemorySize, SMEM_TOTAL_P);

    init_out_kernel<<<(B_SZ * T_STEPS + 255) / 256, 256>>>(out, b_out);
    conv_w_kernel<<<(G4 * H_SZ + 255) / 256, 256>>>(W_hh);
    conv_wih_kernel<<<(G4 * I_SZ + 255) / 256, 256>>>(W_ih);
    split_h0_kernel<<<(B_SZ * H_SZ + 255) / 256, 256>>>(h0);
    split_x_kernel<<<(int)(((size_t)MT * I_SZ + 255) / 256), 256>>>(obs, act);

    dim3 gxg(G4 / 64, MT / 64);
    xg_mma_kernel<<<gxg, 256>>>(b_ih, b_hh);

    dim3 gp(32, 4);
    lstm_persist_kernel<<<gp, 256, SMEM_TOTAL_P>>>(c0, W_out, out);
}

// round 16
// speedup vs baseline: 1.5474x; 1.1264x over previous
#include <cuda_runtime.h>
#include <cuda_fp16.h>
#include <cstdint>
#include <cstddef>

#define T_STEPS 512
#define B_SZ    256
#define H_SZ    512
#define I_SZ    192
#define G4      2048   // 4*H
#define MT      131072 // B*T
#define GROUP_BLOCKS 32

// ---------------------------------------------------------------------------
// Scratch (allocation-free rule: __device__ globals)
// ---------------------------------------------------------------------------
__device__ float    g_xg[(size_t)T_STEPS * B_SZ * G4];  // [T][B][4H] fp32
__device__ __half   g_hh[2][B_SZ * H_SZ];               // h (fp16), double-buffered
__device__ __half   g_wh [(size_t)G4 * H_SZ];           // fp16(W_hh)
__device__ __half   g_xhi[(size_t)MT * I_SZ];           // x hi (fp16)
__device__ __half   g_xlo[(size_t)MT * I_SZ];           // x lo (fp16)
__device__ __half   g_wih[(size_t)G4 * I_SZ];           // fp16(W_ih)
__device__ unsigned g_bars[4][32];                      // per-batch-tile barriers

// ---------------------------------------------------------------------------
// Helpers (sm_80+ baseline instructions only — no 'a'-features)
// ---------------------------------------------------------------------------
__device__ __forceinline__ uint32_t smem_u32(const void* p) {
    uint32_t a;
    asm("{ .reg .u64 t; cvta.to.shared.u64 t, %1; cvt.u32.u64 %0, t; }" : "=r"(a) : "l"(p));
    return a;
}
__device__ __forceinline__ void ldsm_x4(uint32_t r[4], uint32_t addr) {
    asm volatile("ldmatrix.sync.aligned.m8n8.x4.shared.b16 {%0,%1,%2,%3}, [%4];"
                 : "=r"(r[0]), "=r"(r[1]), "=r"(r[2]), "=r"(r[3]) : "r"(addr));
}
__device__ __forceinline__ void ldsm_x2(uint32_t r[2], uint32_t addr) {
    asm volatile("ldmatrix.sync.aligned.m8n8.x2.shared.b16 {%0,%1}, [%2];"
                 : "=r"(r[0]), "=r"(r[1]) : "r"(addr));
}
__device__ __forceinline__ void mma16816(float c[4], const uint32_t a[4], const uint32_t b[2]) {
    asm volatile("mma.sync.aligned.m16n8k16.row.col.f32.f16.f16.f32 "
                 "{%0,%1,%2,%3}, {%4,%5,%6,%7}, {%8,%9}, {%0,%1,%2,%3};"
                 : "+f"(c[0]), "+f"(c[1]), "+f"(c[2]), "+f"(c[3])
                 : "r"(a[0]), "r"(a[1]), "r"(a[2]), "r"(a[3]), "r"(b[0]), "r"(b[1]));
}
#define CP_ASYNC16(saddr, gptr) \
    asm volatile("cp.async.cg.shared.global [%0], [%1], 16;" \
                 :: "r"(saddr), "l"((const void*)(gptr)))
#define CP_COMMIT() asm volatile("cp.async.commit_group;" ::: "memory")

__device__ __forceinline__ unsigned ld_acq(const unsigned* p) {
    unsigned v;
    asm volatile("ld.acquire.gpu.u32 %0, [%1];" : "=r"(v) : "l"(p) : "memory");
    return v;
}
__device__ __forceinline__ void red_release_add(unsigned* p, unsigned v) {
    asm volatile("red.release.gpu.global.add.u32 [%0], %1;" :: "l"(p), "r"(v) : "memory");
}

__device__ __forceinline__ float fsigmoid(float x) {
    return __fdividef(1.0f, 1.0f + __expf(-x));
}
__device__ __forceinline__ float ftanh_fast(float x) {
    return 1.0f - __fdividef(2.0f, 1.0f + __expf(2.0f * x));
}

// ---------------------------------------------------------------------------
// Kernel 0: seed output with bias + reset group barriers
// ---------------------------------------------------------------------------
__global__ void init_out_kernel(float* __restrict__ out, const float* __restrict__ b_out) {
    int i = blockIdx.x * blockDim.x + threadIdx.x;
    if (i < 128) ((unsigned*)g_bars)[i] = 0u;
    if (i < B_SZ * T_STEPS) out[i] = b_out[0];
}

// ---------------------------------------------------------------------------
// Split / convert kernels
// ---------------------------------------------------------------------------
__global__ void conv_w_kernel(const float* __restrict__ W) {
    int i = blockIdx.x * blockDim.x + threadIdx.x;
    if (i < G4 * H_SZ) g_wh[i] = __float2half(W[i]);
}
__global__ void conv_wih_kernel(const float* __restrict__ W) {
    int i = blockIdx.x * blockDim.x + threadIdx.x;
    if (i < G4 * I_SZ) g_wih[i] = __float2half(W[i]);
}
__global__ void split_h0_kernel(const float* __restrict__ h0) {
    int i = blockIdx.x * blockDim.x + threadIdx.x;
    if (i < B_SZ * H_SZ)
        g_hh[1][i] = __float2half(h0[i]);   // t=0 reads buffer (0+1)&1 = 1
}
__global__ void split_x_kernel(const float* __restrict__ obs, const float* __restrict__ act) {
    size_t i = (size_t)blockIdx.x * blockDim.x + threadIdx.x;
    if (i >= (size_t)MT * I_SZ) return;
    int m = (int)(i / I_SZ), k = (int)(i % I_SZ);
    int b = m >> 9, t = m & 511;
    float v = (k < 128) ? obs[((size_t)(b * T_STEPS + t)) * 128 + k]
                        : act[((size_t)(b * T_STEPS + t)) * 64 + (k - 128)];
    __half hi = __float2half(v);
    g_xhi[i] = hi;
    g_xlo[i] = __float2half(v - __half2float(hi));
}

// ---------------------------------------------------------------------------
// Kernel 1: xg GEMM, 2-term fp16 split HMMA (verified R12). Tile 64x64, K=192.
// ---------------------------------------------------------------------------
struct __align__(16) TileSmem {
    union {
        struct {
            __half Ahi[4][64][24];   // [k16][m][16 valid + 8 pad]
            __half Alo[4][64][24];
            __half Bh [4][64][24];
        };
        float Cx[64][65];
    };
};

__global__ void __launch_bounds__(256)
xg_mma_kernel(const float* __restrict__ b_ih, const float* __restrict__ b_hh) {
    __shared__ TileSmem sm;
    const int tid  = threadIdx.x;
    const int wid  = tid >> 5;
    const int lane = tid & 31;
    const int n0     = blockIdx.x * 64;
    const int m_base = blockIdx.y * 64;

    const int mw = wid >> 1;
    const int nw = wid & 1;
    const int m0 = mw * 16;
    const int a_row = m0 + (lane & 7) + 8 * ((lane >> 3) & 1);
    const int a_kh  = 8 * (lane >> 4);
    const int a_off = a_row * 24 + a_kh;
    const int b_lane = lane & 15;
    const int b_row0 = nw * 32 + (b_lane & 7);
    const int b_kh   = 8 * ((b_lane >> 3) & 1);

    const uint32_t sAhi = smem_u32(&sm.Ahi[0][0][0]);
    const uint32_t sAlo = smem_u32(&sm.Alo[0][0][0]);
    const uint32_t sBh  = smem_u32(&sm.Bh [0][0][0]);

    float c[4][4] = {};

    for (int kc = 0; kc < 3; kc++) {
        #pragma unroll
        for (int i = 0; i < 2; i++) {
            int flat = tid + i * 256;
            int row = flat >> 3, q = flat & 7;
            size_t ga = (size_t)(m_base + row) * I_SZ + kc * 64 + q * 8;
            uint4 va_hi = *reinterpret_cast<const uint4*>(g_xhi + ga);
            uint4 va_lo = *reinterpret_cast<const uint4*>(g_xlo + ga);
            *reinterpret_cast<uint4*>(&sm.Ahi[q >> 1][row][(q & 1) * 8]) = va_hi;
            *reinterpret_cast<uint4*>(&sm.Alo[q >> 1][row][(q & 1) * 8]) = va_lo;
            size_t gb = (size_t)(n0 + row) * I_SZ + kc * 64 + q * 8;
            uint4 vb = *reinterpret_cast<const uint4*>(g_wih + gb);
            *reinterpret_cast<uint4*>(&sm.Bh[q >> 1][row][(q & 1) * 8]) = vb;
        }
        __syncthreads();
        #pragma unroll
        for (int ks = 0; ks < 4; ks++) {
            const uint32_t plane = (uint32_t)ks * 3072;
            uint32_t ahi[4], alo[4];
            ldsm_x4(ahi, sAhi + plane + a_off * 2);
            ldsm_x4(alo, sAlo + plane + a_off * 2);
            #pragma unroll
            for (int g4 = 0; g4 < 4; g4++) {
                uint32_t bh[2];
                uint32_t boff = plane + ((b_row0 + g4 * 8) * 24 + b_kh) * 2;
                ldsm_x2(bh, sBh + boff);
                mma16816(c[g4], ahi, bh);
                mma16816(c[g4], alo, bh);
            }
        }
        __syncthreads();
    }

    {
        const int g  = lane >> 2;
        const int tq = lane & 3;
        #pragma unroll
        for (int g4 = 0; g4 < 4; g4++) {
            int n = nw * 32 + g4 * 8 + 2 * tq;
            sm.Cx[m0 + g][n]         = c[g4][0];
            sm.Cx[m0 + g][n + 1]     = c[g4][1];
            sm.Cx[m0 + g + 8][n]     = c[g4][2];
            sm.Cx[m0 + g + 8][n + 1] = c[g4][3];
        }
    }
    __syncthreads();

    const int m  = tid >> 2;
    const int cg = tid & 3;
    const int gm = m_base + m;
    const int b  = gm >> 9, tt = gm & 511;
    float* dst = g_xg + ((size_t)tt * B_SZ + b) * G4 + n0 + cg * 16;
    #pragma unroll
    for (int u4 = 0; u4 < 4; u4++) {
        float4 v;
        int nl = cg * 16 + u4 * 4;
        int n  = n0 + nl;
        v.x = sm.Cx[m][nl + 0] + b_ih[n + 0] + b_hh[n + 0];
        v.y = sm.Cx[m][nl + 1] + b_ih[n + 1] + b_hh[n + 1];
        v.z = sm.Cx[m][nl + 2] + b_ih[n + 2] + b_hh[n + 2];
        v.w = sm.Cx[m][nl + 3] + b_ih[n + 3] + b_hh[n + 3];
        *reinterpret_cast<float4*>(dst + u4 * 4) = v;
    }
}

// ---------------------------------------------------------------------------
// Kernel 2: PERSISTENT recurrence. Grid (32, 4) = 128 blocks, 256 thr.
// fp16(W_hh) resident (64 KB smem). h = plain fp16, 1-term GEMM.
// K=512 in TWO chunks of 256 (2 stages x 48 KB), both issued up-front.
// R16 deltas vs R15 (arithmetic/order bit-identical):
//   - W fragments via ldmatrix.x4 (2 g4 groups per load): W-LDSM halved.
//   - group-barrier wait = all-thread ld.acquire spin (no tid0+syncthreads).
//   - publish via red.release.gpu (replaces __threadfence + atomicAdd);
//     out-atomic + xg prefetch moved after the release, off critical path.
// Dynamic smem: [0,64K) W | [64K,64K+96K) stages. Cx aliases stage 0.
// ---------------------------------------------------------------------------
#define W_BYTES      65536
#define ASTAGE_OFF   65536
#define ASTAGE_BYTES 49152
#define SMEM_TOTAL_P (ASTAGE_OFF + 2 * ASTAGE_BYTES)

__global__ void __launch_bounds__(256, 1)
lstm_persist_kernel(const float* __restrict__ c0,
                    const float* __restrict__ W_out,
                    float* __restrict__ out) {
    extern __shared__ uint8_t dynsmem[];
    const uint32_t dyn = smem_u32(dynsmem);
    const int tid  = threadIdx.x;
    const int wid  = tid >> 5;
    const int lane = tid & 31;
    const int j0     = blockIdx.x * 16;
    const int by     = blockIdx.y;
    const int m_base = by * 64;

    // ---- load resident fp16 W (once): 4096 16B-chunks ----
    for (int idx = tid; idx < 4096; idx += 256) {
        int k16 = idx >> 7;
        int rem = idx & 127;
        int row = rem >> 1;
        int half = rem & 1;
        int gate = row >> 4, jj = row & 15;
        size_t g = (size_t)(gate * H_SZ + j0 + jj) * H_SZ + k16 * 16 + half * 8;
        uint32_t off = (uint32_t)(k16 * 2048 +
                       ((row * 32 + half * 16) ^ (((row >> 2) & 1) << 4)));
        *reinterpret_cast<uint4*>(dynsmem + off) =
            *reinterpret_cast<const uint4*>(g_wh + g);
    }
    __syncthreads();

    // ---- per-lane constants ----
    const int mw = wid >> 1;
    const int nw = wid & 1;
    const int m0 = mw * 16;
    const int a_row = m0 + (lane & 7) + 8 * ((lane >> 3) & 1);
    const int a_kh  = 8 * (lane >> 4);
    const uint32_t a_off2 = (uint32_t)(a_row * 24 + a_kh) * 2;
    // W x4 per-lane address: row = nw*32 + (lane&7) + 8*((lane>>4)&1),
    // khalf 16B from (lane>>3)&1; swizzle parity = (lane>>2)&1 (invariant
    // under +8/+16 row shifts since (row>>2)&1 is unchanged).
    const int w_row = nw * 32 + (lane & 7) + 8 * ((lane >> 4) & 1);
    const uint32_t wB4 = dyn + (uint32_t)(w_row * 32) +
        ((uint32_t)(16 * ((lane >> 3) & 1)) ^ ((((uint32_t)lane >> 2) & 1u) << 4));

    const int em = tid >> 2;
    const int jg = tid & 3;
    const int eb = m_base + em;
    float (*Cx)[65] = reinterpret_cast<float (*)[65]>(dynsmem + ASTAGE_OFF);
    const unsigned* barp = (const unsigned*)&g_bars[by][0];

    // cell state + W_out in registers
    float creg[4], wout_r[4];
    #pragma unroll
    for (int u = 0; u < 4; u++) {
        creg[u]   = c0[(size_t)eb * H_SZ + j0 + jg * 4 + u];
        wout_r[u] = W_out[j0 + jg * 4 + u];
    }

    // prologue: prefetch xg for t=0
    float xg_r[4][4];
    {
        const float* xg_t = g_xg + (size_t)eb * G4;
        #pragma unroll
        for (int g = 0; g < 4; g++)
            *reinterpret_cast<float4*>(xg_r[g]) =
                *reinterpret_cast<const float4*>(xg_t + g * H_SZ + j0 + jg * 4);
    }

    for (int t = 0; t < T_STEPS; t++) {
        // ---- all-thread acquire spin on group flag (broadcast L2 reads) ----
        if (t > 0) {
            const unsigned target = (unsigned)GROUP_BLOCKS * (unsigned)t;
            while (ld_acq(barp) < target) { }
        }

        const __half* hh = g_hh[(t + 1) & 1];
        const int cb = t & 1;

        // chunk kc covers k = kc*256 .. +255; 2048 16B transfers, 8/thread.
        auto issue_chunk = [&](int kc) {
            const uint32_t sb = dyn + ASTAGE_OFF + (uint32_t)kc * ASTAGE_BYTES;
            #pragma unroll
            for (int j = 0; j < 8; j++) {
                const int flat = tid + j * 256;
                const int row = flat >> 5;
                const int q   = flat & 31;
                const uint32_t soff =
                    (uint32_t)((q >> 1) * 3072 + row * 48 + (q & 1) * 16);
                size_t ga = (size_t)(m_base + row) * H_SZ + kc * 256 + q * 8;
                CP_ASYNC16(sb + soff, hh + ga);
            }
            CP_COMMIT();
        };

        issue_chunk(0);
        issue_chunk(1);

        float c[4][4] = {};

        #pragma unroll
        for (int kc = 0; kc < 2; kc++) {
            if (kc == 0) asm volatile("cp.async.wait_group 1;" ::: "memory");
            else         asm volatile("cp.async.wait_group 0;" ::: "memory");
            __syncthreads();

            const uint32_t sb = dyn + ASTAGE_OFF + (uint32_t)kc * ASTAGE_BYTES;
            #pragma unroll
            for (int ks = 0; ks < 16; ks++) {
                const uint32_t aplane = sb + (uint32_t)ks * 3072;
                const uint32_t wplane = (uint32_t)(kc * 16 + ks) * 2048;
                uint32_t ahi[4];
                ldsm_x4(ahi, aplane + a_off2);
                #pragma unroll
                for (int g4p = 0; g4p < 2; g4p++) {
                    uint32_t bh4[4];
                    ldsm_x4(bh4, wB4 + wplane + (uint32_t)(g4p * 512));
                    mma16816(c[2 * g4p],     ahi, bh4);
                    mma16816(c[2 * g4p + 1], ahi, bh4 + 2);
                }
            }
        }

        // fragments -> Cx: no barrier needed (stage-0 reads done before all
        // threads passed the chunk-1 barrier; chunk-1 reads stage-1 only)
        {
            const int g  = lane >> 2;
            const int tq = lane & 3;
            #pragma unroll
            for (int g4 = 0; g4 < 4; g4++) {
                int n = nw * 32 + g4 * 8 + 2 * tq;
                Cx[m0 + g][n]         = c[g4][0];
                Cx[m0 + g][n + 1]     = c[g4][1];
                Cx[m0 + g + 8][n]     = c[g4][2];
                Cx[m0 + g + 8][n + 1] = c[g4][3];
            }
        }
        __syncthreads();

        // ---- epilogue: thread owns (em, 4 j's); c, W_out in registers ----
        float s = 0.f;
        uint32_t h_pack[2];
        #pragma unroll
        for (int u = 0; u < 4; u++) {
            const int jj = jg * 4 + u;
            float gi = Cx[em][0 * 16 + jj] + xg_r[0][u];
            float gf = Cx[em][1 * 16 + jj] + xg_r[1][u];
            float gg = Cx[em][2 * 16 + jj] + xg_r[2][u];
            float go = Cx[em][3 * 16 + jj] + xg_r[3][u];
            gi = fsigmoid(gi);
            gf = fsigmoid(gf);
            gg = ftanh_fast(gg);
            go = fsigmoid(go);
            float cn = gf * creg[u] + gi * gg;
            creg[u] = cn;
            float hv = go * ftanh_fast(cn);
            s += hv * wout_r[u];
            uint32_t uh = (uint32_t)__half_as_ushort(__float2half(hv));
            if (u & 1) h_pack[u >> 1] |= uh << 16;
            else       h_pack[u >> 1]  = uh;
        }
        size_t ho = (size_t)eb * H_SZ + j0 + jg * 4;
        *reinterpret_cast<uint2*>(&g_hh[cb][ho]) = make_uint2(h_pack[0], h_pack[1]);

        // ---- publish h(t): bar.sync (cta-order) -> tid0 release-add ----
        __syncthreads();
        if (tid == 0) red_release_add(&g_bars[by][0], 1u);

        // off the critical path: fused out projection + next-xg prefetch
        s += __shfl_xor_sync(0xffffffffu, s, 1);
        s += __shfl_xor_sync(0xffffffffu, s, 2);
        if (jg == 0) atomicAdd(&out[(size_t)eb * T_STEPS + t], s);
        if (t + 1 < T_STEPS) {
            const float* xg_t = g_xg + (size_t)(t + 1) * B_SZ * G4 + (size_t)eb * G4;
            #pragma unroll
            for (int g = 0; g < 4; g++)
                *reinterpret_cast<float4*>(xg_r[g]) =
                    *reinterpret_cast<const float4*>(xg_t + g * H_SZ + j0 + jg * 4);
        }
    }
}

// ---------------------------------------------------------------------------
extern "C" void kernel_launch(void* const* d_in, const int* in_sizes, int n_in,
                              void* d_out, int out_size) {
    const float* obs   = (const float*)d_in[0];
    const float* act   = (const float*)d_in[1];
    const float* h0    = (const float*)d_in[2];
    const float* c0    = (const float*)d_in[3];
    const float* W_ih  = (const float*)d_in[4];
    const float* W_hh  = (const float*)d_in[5];
    const float* b_ih  = (const float*)d_in[6];
    const float* b_hh  = (const float*)d_in[7];
    const float* W_out = (const float*)d_in[8];
    const float* b_out = (const float*)d_in[9];
    float* out = (float*)d_out;

    cudaFuncSetAttribute(lstm_persist_kernel,
                         cudaFuncAttributeMaxDynamicSharedMemorySize, SMEM_TOTAL_P);

    init_out_kernel<<<(B_SZ * T_STEPS + 255) / 256, 256>>>(out, b_out);
    conv_w_kernel<<<(G4 * H_SZ + 255) / 256, 256>>>(W_hh);
    conv_wih_kernel<<<(G4 * I_SZ + 255) / 256, 256>>>(W_ih);
    split_h0_kernel<<<(B_SZ * H_SZ + 255) / 256, 256>>>(h0);
    split_x_kernel<<<(int)(((size_t)MT * I_SZ + 255) / 256), 256>>>(obs, act);

    dim3 gxg(G4 / 64, MT / 64);
    xg_mma_kernel<<<gxg, 256>>>(b_ih, b_hh);

    dim3 gp(32, 4);
    lstm_persist_kernel<<<gp, 256, SMEM_TOTAL_P>>>(c0, W_out, out);
}

// round 17
// speedup vs baseline: 1.7323x; 1.1195x over previous
#include <cuda_runtime.h>
#include <cuda_fp16.h>
#include <cstdint>
#include <cstddef>

#define T_STEPS 512
#define B_SZ    256
#define H_SZ    512
#define I_SZ    192
#define G4      2048   // 4*H
#define MT      131072 // B*T
#define GROUP_BLOCKS 32

// ---------------------------------------------------------------------------
// Scratch (allocation-free rule: __device__ globals)
// ---------------------------------------------------------------------------
__device__ __half   g_xg[(size_t)T_STEPS * B_SZ * G4];  // [T][B][4H] fp16
__device__ __half   g_hh[2][B_SZ * H_SZ];               // h (fp16), double-buffered
__device__ __half   g_wh [(size_t)G4 * H_SZ];           // fp16(W_hh)
__device__ __half   g_xhi[(size_t)MT * I_SZ];           // x hi (fp16)
__device__ __half   g_xlo[(size_t)MT * I_SZ];           // x lo (fp16)
__device__ __half   g_wih[(size_t)G4 * I_SZ];           // fp16(W_ih)
__device__ float    g_bias[G4];                         // b_ih + b_hh
__device__ unsigned g_bars[4][32];                      // per-batch-tile barriers

// ---------------------------------------------------------------------------
// Helpers (sm_80+ baseline instructions only — no 'a'-features)
// ---------------------------------------------------------------------------
__device__ __forceinline__ uint32_t smem_u32(const void* p) {
    uint32_t a;
    asm("{ .reg .u64 t; cvta.to.shared.u64 t, %1; cvt.u32.u64 %0, t; }" : "=r"(a) : "l"(p));
    return a;
}
__device__ __forceinline__ void ldsm_x4(uint32_t r[4], uint32_t addr) {
    asm volatile("ldmatrix.sync.aligned.m8n8.x4.shared.b16 {%0,%1,%2,%3}, [%4];"
                 : "=r"(r[0]), "=r"(r[1]), "=r"(r[2]), "=r"(r[3]) : "r"(addr));
}
__device__ __forceinline__ void mma16816(float c[4], const uint32_t a[4], const uint32_t b[2]) {
    asm volatile("mma.sync.aligned.m16n8k16.row.col.f32.f16.f16.f32 "
                 "{%0,%1,%2,%3}, {%4,%5,%6,%7}, {%8,%9}, {%0,%1,%2,%3};"
                 : "+f"(c[0]), "+f"(c[1]), "+f"(c[2]), "+f"(c[3])
                 : "r"(a[0]), "r"(a[1]), "r"(a[2]), "r"(a[3]), "r"(b[0]), "r"(b[1]));
}
#define CP_ASYNC16(saddr, gptr) \
    asm volatile("cp.async.cg.shared.global [%0], [%1], 16;" \
                 :: "r"(saddr), "l"((const void*)(gptr)))
#define CP_COMMIT() asm volatile("cp.async.commit_group;" ::: "memory")

__device__ __forceinline__ unsigned ld_acq(const unsigned* p) {
    unsigned v;
    asm volatile("ld.acquire.gpu.u32 %0, [%1];" : "=r"(v) : "l"(p) : "memory");
    return v;
}
__device__ __forceinline__ void red_release_add(unsigned* p, unsigned v) {
    asm volatile("red.release.gpu.global.add.u32 [%0], %1;" :: "l"(p), "r"(v) : "memory");
}

// Fast activations via MUFU.TANH (sm_75+): halves MUFU count vs exp+rcp.
__device__ __forceinline__ float tanhapx(float x) {
    float y;
    asm("tanh.approx.f32 %0, %1;" : "=f"(y) : "f"(x));
    return y;
}
__device__ __forceinline__ float fsigmoid(float x) {
    return fmaf(0.5f, tanhapx(0.5f * x), 0.5f);
}

// ---------------------------------------------------------------------------
// Kernel 0: seed output with bias + reset group barriers
// ---------------------------------------------------------------------------
__global__ void init_out_kernel(float* __restrict__ out, const float* __restrict__ b_out) {
    int i = blockIdx.x * blockDim.x + threadIdx.x;
    if (i < 128) ((unsigned*)g_bars)[i] = 0u;
    if (i < B_SZ * T_STEPS) out[i] = b_out[0];
}

// ---------------------------------------------------------------------------
// Split / convert kernels
// ---------------------------------------------------------------------------
__global__ void conv_w_kernel(const float* __restrict__ W) {
    int i = blockIdx.x * blockDim.x + threadIdx.x;
    if (i < G4 * H_SZ) g_wh[i] = __float2half(W[i]);
}
__global__ void conv_wih_kernel(const float* __restrict__ W,
                                const float* __restrict__ b_ih,
                                const float* __restrict__ b_hh) {
    int i = blockIdx.x * blockDim.x + threadIdx.x;
    if (i < G4 * I_SZ) g_wih[i] = __float2half(W[i]);
    if (i < G4) g_bias[i] = b_ih[i] + b_hh[i];
}
__global__ void split_h0_kernel(const float* __restrict__ h0) {
    int i = blockIdx.x * blockDim.x + threadIdx.x;
    if (i < B_SZ * H_SZ)
        g_hh[1][i] = __float2half(h0[i]);   // t=0 reads buffer (0+1)&1 = 1
}
__global__ void split_x_kernel(const float* __restrict__ obs, const float* __restrict__ act) {
    size_t i = (size_t)blockIdx.x * blockDim.x + threadIdx.x;
    if (i >= (size_t)MT * I_SZ) return;
    int m = (int)(i / I_SZ), k = (int)(i % I_SZ);
    int b = m >> 9, t = m & 511;
    float v = (k < 128) ? obs[((size_t)(b * T_STEPS + t)) * 128 + k]
                        : act[((size_t)(b * T_STEPS + t)) * 64 + (k - 128)];
    __half hi = __float2half(v);
    g_xhi[i] = hi;
    g_xlo[i] = __float2half(v - __half2float(hi));
}

// ---------------------------------------------------------------------------
// Kernel 1: xg GEMM, 2-term fp16 split HMMA. Tile M=64 x N=128, K=192.
// N=128 halves the A-tile L2 traffic vs N=64 (16 n-blocks instead of 32).
// B fragments via the R16-verified ldmatrix-x4 lane pattern. Output fp16.
// ---------------------------------------------------------------------------
struct __align__(16) TileSmemX {
    union {
        struct {
            __half Ahi[4][64][24];    // 12288 B
            __half Alo[4][64][24];    // 12288 B
            __half Bh [4][128][24];   // 24576 B
        };
        float Cx[64][132];            // 33792 B (aliases tiles)
    };
};

__global__ void __launch_bounds__(256)
xg_mma_kernel() {
    __shared__ TileSmemX sm;
    const int tid  = threadIdx.x;
    const int wid  = tid >> 5;
    const int lane = tid & 31;
    const int n0     = blockIdx.x * 128;
    const int m_base = blockIdx.y * 64;

    const int mw = wid >> 1;   // 4 m-warp-tiles of 16
    const int nw = wid & 1;    // 2 n-warp-tiles of 64
    const int m0 = mw * 16;
    const int a_row = m0 + (lane & 7) + 8 * ((lane >> 3) & 1);
    const int a_kh  = 8 * (lane >> 4);
    const uint32_t a_off2 = (uint32_t)(a_row * 24 + a_kh) * 2;
    // B x4 lane address (R16-verified pattern): rows r..r+7 (k-lo), r..r+7
    // (k-hi), r+8..r+15 (k-lo), r+8..r+15 (k-hi).
    const int b4row  = nw * 64 + (lane & 7) + 8 * ((lane >> 4) & 1);
    const uint32_t sBh = smem_u32(&sm.Bh[0][0][0]);
    const uint32_t b4addr = sBh + (uint32_t)(b4row * 24 + ((lane >> 3) & 1) * 8) * 2;

    const uint32_t sAhi = smem_u32(&sm.Ahi[0][0][0]);
    const uint32_t sAlo = smem_u32(&sm.Alo[0][0][0]);

    float c[8][4] = {};

    for (int kc = 0; kc < 3; kc++) {
        #pragma unroll
        for (int i = 0; i < 2; i++) {
            int flat = tid + i * 256;
            int row = flat >> 3, q = flat & 7;
            size_t ga = (size_t)(m_base + row) * I_SZ + kc * 64 + q * 8;
            *reinterpret_cast<uint4*>(&sm.Ahi[q >> 1][row][(q & 1) * 8]) =
                *reinterpret_cast<const uint4*>(g_xhi + ga);
            *reinterpret_cast<uint4*>(&sm.Alo[q >> 1][row][(q & 1) * 8]) =
                *reinterpret_cast<const uint4*>(g_xlo + ga);
        }
        #pragma unroll
        for (int i = 0; i < 4; i++) {
            int flat = tid + i * 256;
            int row = flat >> 3, q = flat & 7;   // row 0..127
            size_t gb = (size_t)(n0 + row) * I_SZ + kc * 64 + q * 8;
            *reinterpret_cast<uint4*>(&sm.Bh[q >> 1][row][(q & 1) * 8]) =
                *reinterpret_cast<const uint4*>(g_wih + gb);
        }
        __syncthreads();
        #pragma unroll
        for (int ks = 0; ks < 4; ks++) {
            const uint32_t aplane = (uint32_t)ks * 3072;
            const uint32_t bplane = (uint32_t)ks * 6144;
            uint32_t ahi[4], alo[4];
            ldsm_x4(ahi, sAhi + aplane + a_off2);
            ldsm_x4(alo, sAlo + aplane + a_off2);
            #pragma unroll
            for (int g4p = 0; g4p < 4; g4p++) {
                uint32_t bh4[4];
                ldsm_x4(bh4, b4addr + bplane + (uint32_t)(g4p * 768));
                mma16816(c[2 * g4p],     ahi, bh4);
                mma16816(c[2 * g4p],     alo, bh4);
                mma16816(c[2 * g4p + 1], ahi, bh4 + 2);
                mma16816(c[2 * g4p + 1], alo, bh4 + 2);
            }
        }
        __syncthreads();
    }

    {
        const int g  = lane >> 2;
        const int tq = lane & 3;
        #pragma unroll
        for (int g4 = 0; g4 < 8; g4++) {
            int n = nw * 64 + g4 * 8 + 2 * tq;
            sm.Cx[m0 + g][n]         = c[g4][0];
            sm.Cx[m0 + g][n + 1]     = c[g4][1];
            sm.Cx[m0 + g + 8][n]     = c[g4][2];
            sm.Cx[m0 + g + 8][n + 1] = c[g4][3];
        }
    }
    __syncthreads();

    // epilogue: thread owns row m = tid>>2, 32 cols at (tid&3)*32; fp16 out.
    const int m  = tid >> 2;
    const int cq = tid & 3;
    const int gm = m_base + m;
    const int b  = gm >> 9, tt = gm & 511;
    __half* dst = g_xg + ((size_t)tt * B_SZ + b) * G4 + n0 + cq * 32;
    #pragma unroll
    for (int u8 = 0; u8 < 4; u8++) {
        const int col = cq * 32 + u8 * 8;
        float4 b0 = *reinterpret_cast<const float4*>(g_bias + n0 + col);
        float4 b1 = *reinterpret_cast<const float4*>(g_bias + n0 + col + 4);
        __half hbuf[8];
        hbuf[0] = __float2half(sm.Cx[m][col + 0] + b0.x);
        hbuf[1] = __float2half(sm.Cx[m][col + 1] + b0.y);
        hbuf[2] = __float2half(sm.Cx[m][col + 2] + b0.z);
        hbuf[3] = __float2half(sm.Cx[m][col + 3] + b0.w);
        hbuf[4] = __float2half(sm.Cx[m][col + 4] + b1.x);
        hbuf[5] = __float2half(sm.Cx[m][col + 5] + b1.y);
        hbuf[6] = __float2half(sm.Cx[m][col + 6] + b1.z);
        hbuf[7] = __float2half(sm.Cx[m][col + 7] + b1.w);
        *reinterpret_cast<uint4*>(dst + u8 * 8) = *reinterpret_cast<uint4*>(hbuf);
    }
}

// ---------------------------------------------------------------------------
// Kernel 2: PERSISTENT recurrence (structure identical to R16 WIN).
// Grid (32, 4) = 128 blocks, 256 thr. fp16(W_hh) resident (64 KB smem).
// K=512 in TWO chunks of 256 (2 stages x 48 KB), issued up-front.
// xg now fp16 (uint2 prefetch); epilogue via tanh.approx (MUFU halved).
// Dynamic smem: [0,64K) W | [64K,64K+96K) stages. Cx aliases stage 0.
// ---------------------------------------------------------------------------
#define W_BYTES      65536
#define ASTAGE_OFF   65536
#define ASTAGE_BYTES 49152
#define SMEM_TOTAL_P (ASTAGE_OFF + 2 * ASTAGE_BYTES)

__global__ void __launch_bounds__(256, 1)
lstm_persist_kernel(const float* __restrict__ c0,
                    const float* __restrict__ W_out,
                    float* __restrict__ out) {
    extern __shared__ uint8_t dynsmem[];
    const uint32_t dyn = smem_u32(dynsmem);
    const int tid  = threadIdx.x;
    const int wid  = tid >> 5;
    const int lane = tid & 31;
    const int j0     = blockIdx.x * 16;
    const int by     = blockIdx.y;
    const int m_base = by * 64;

    // ---- load resident fp16 W (once): 4096 16B-chunks ----
    for (int idx = tid; idx < 4096; idx += 256) {
        int k16 = idx >> 7;
        int rem = idx & 127;
        int row = rem >> 1;
        int half = rem & 1;
        int gate = row >> 4, jj = row & 15;
        size_t g = (size_t)(gate * H_SZ + j0 + jj) * H_SZ + k16 * 16 + half * 8;
        uint32_t off = (uint32_t)(k16 * 2048 +
                       ((row * 32 + half * 16) ^ (((row >> 2) & 1) << 4)));
        *reinterpret_cast<uint4*>(dynsmem + off) =
            *reinterpret_cast<const uint4*>(g_wh + g);
    }
    __syncthreads();

    // ---- per-lane constants ----
    const int mw = wid >> 1;
    const int nw = wid & 1;
    const int m0 = mw * 16;
    const int a_row = m0 + (lane & 7) + 8 * ((lane >> 3) & 1);
    const int a_kh  = 8 * (lane >> 4);
    const uint32_t a_off2 = (uint32_t)(a_row * 24 + a_kh) * 2;
    const int w_row = nw * 32 + (lane & 7) + 8 * ((lane >> 4) & 1);
    const uint32_t wB4 = dyn + (uint32_t)(w_row * 32) +
        ((uint32_t)(16 * ((lane >> 3) & 1)) ^ ((((uint32_t)lane >> 2) & 1u) << 4));

    const int em = tid >> 2;
    const int jg = tid & 3;
    const int eb = m_base + em;
    float (*Cx)[65] = reinterpret_cast<float (*)[65]>(dynsmem + ASTAGE_OFF);
    const unsigned* barp = (const unsigned*)&g_bars[by][0];

    // cell state + W_out in registers
    float creg[4], wout_r[4];
    #pragma unroll
    for (int u = 0; u < 4; u++) {
        creg[u]   = c0[(size_t)eb * H_SZ + j0 + jg * 4 + u];
        wout_r[u] = W_out[j0 + jg * 4 + u];
    }

    // prologue: prefetch xg (fp16, uint2 = 4 halfs per gate) for t=0
    uint2 xg_p[4];
    {
        const __half* xg_t = g_xg + (size_t)eb * G4;
        #pragma unroll
        for (int g = 0; g < 4; g++)
            xg_p[g] = *reinterpret_cast<const uint2*>(xg_t + g * H_SZ + j0 + jg * 4);
    }

    for (int t = 0; t < T_STEPS; t++) {
        // ---- all-thread acquire spin on group flag (broadcast L2 reads) ----
        if (t > 0) {
            const unsigned target = (unsigned)GROUP_BLOCKS * (unsigned)t;
            while (ld_acq(barp) < target) { }
        }

        const __half* hh = g_hh[(t + 1) & 1];
        const int cb = t & 1;

        auto issue_chunk = [&](int kc) {
            const uint32_t sb = dyn + ASTAGE_OFF + (uint32_t)kc * ASTAGE_BYTES;
            #pragma unroll
            for (int j = 0; j < 8; j++) {
                const int flat = tid + j * 256;
                const int row = flat >> 5;
                const int q   = flat & 31;
                const uint32_t soff =
                    (uint32_t)((q >> 1) * 3072 + row * 48 + (q & 1) * 16);
                size_t ga = (size_t)(m_base + row) * H_SZ + kc * 256 + q * 8;
                CP_ASYNC16(sb + soff, hh + ga);
            }
            CP_COMMIT();
        };

        issue_chunk(0);
        issue_chunk(1);

        float c[4][4] = {};

        #pragma unroll
        for (int kc = 0; kc < 2; kc++) {
            if (kc == 0) asm volatile("cp.async.wait_group 1;" ::: "memory");
            else         asm volatile("cp.async.wait_group 0;" ::: "memory");
            __syncthreads();

            const uint32_t sb = dyn + ASTAGE_OFF + (uint32_t)kc * ASTAGE_BYTES;
            #pragma unroll
            for (int ks = 0; ks < 16; ks++) {
                const uint32_t aplane = sb + (uint32_t)ks * 3072;
                const uint32_t wplane = (uint32_t)(kc * 16 + ks) * 2048;
                uint32_t ahi[4];
                ldsm_x4(ahi, aplane + a_off2);
                #pragma unroll
                for (int g4p = 0; g4p < 2; g4p++) {
                    uint32_t bh4[4];
                    ldsm_x4(bh4, wB4 + wplane + (uint32_t)(g4p * 512));
                    mma16816(c[2 * g4p],     ahi, bh4);
                    mma16816(c[2 * g4p + 1], ahi, bh4 + 2);
                }
            }
        }

        // fragments -> Cx: no barrier needed (stage-0 reads done before all
        // threads passed the chunk-1 barrier; chunk-1 reads stage-1 only)
        {
            const int g  = lane >> 2;
            const int tq = lane & 3;
            #pragma unroll
            for (int g4 = 0; g4 < 4; g4++) {
                int n = nw * 32 + g4 * 8 + 2 * tq;
                Cx[m0 + g][n]         = c[g4][0];
                Cx[m0 + g][n + 1]     = c[g4][1];
                Cx[m0 + g + 8][n]     = c[g4][2];
                Cx[m0 + g + 8][n + 1] = c[g4][3];
            }
        }
        __syncthreads();

        // ---- epilogue: thread owns (em, 4 j's); c, W_out in registers ----
        float s = 0.f;
        uint32_t h_pack[2];
        #pragma unroll
        for (int u = 0; u < 4; u++) {
            const int jj = jg * 4 + u;
            float gi = Cx[em][0 * 16 + jj] +
                       __half2float(reinterpret_cast<const __half*>(&xg_p[0])[u]);
            float gf = Cx[em][1 * 16 + jj] +
                       __half2float(reinterpret_cast<const __half*>(&xg_p[1])[u]);
            float gg = Cx[em][2 * 16 + jj] +
                       __half2float(reinterpret_cast<const __half*>(&xg_p[2])[u]);
            float go = Cx[em][3 * 16 + jj] +
                       __half2float(reinterpret_cast<const __half*>(&xg_p[3])[u]);
            gi = fsigmoid(gi);
            gf = fsigmoid(gf);
            gg = tanhapx(gg);
            go = fsigmoid(go);
            float cn = gf * creg[u] + gi * gg;
            creg[u] = cn;
            float hv = go * tanhapx(cn);
            s += hv * wout_r[u];
            uint32_t uh = (uint32_t)__half_as_ushort(__float2half(hv));
            if (u & 1) h_pack[u >> 1] |= uh << 16;
            else       h_pack[u >> 1]  = uh;
        }
        size_t ho = (size_t)eb * H_SZ + j0 + jg * 4;
        *reinterpret_cast<uint2*>(&g_hh[cb][ho]) = make_uint2(h_pack[0], h_pack[1]);

        // ---- publish h(t): bar.sync (cta-order) -> tid0 release-add ----
        __syncthreads();
        if (tid == 0) red_release_add(&g_bars[by][0], 1u);

        // off the critical path: fused out projection + next-xg prefetch
        s += __shfl_xor_sync(0xffffffffu, s, 1);
        s += __shfl_xor_sync(0xffffffffu, s, 2);
        if (jg == 0) atomicAdd(&out[(size_t)eb * T_STEPS + t], s);
        if (t + 1 < T_STEPS) {
            const __half* xg_t = g_xg + ((size_t)(t + 1) * B_SZ + eb) * G4;
            #pragma unroll
            for (int g = 0; g < 4; g++)
                xg_p[g] = *reinterpret_cast<const uint2*>(xg_t + g * H_SZ + j0 + jg * 4);
        }
    }
}

// ---------------------------------------------------------------------------
extern "C" void kernel_launch(void* const* d_in, const int* in_sizes, int n_in,
                              void* d_out, int out_size) {
    const float* obs   = (const float*)d_in[0];
    const float* act   = (const float*)d_in[1];
    const float* h0    = (const float*)d_in[2];
    const float* c0    = (const float*)d_in[3];
    const float* W_ih  = (const float*)d_in[4];
    const float* W_hh  = (const float*)d_in[5];
    const float* b_ih  = (const float*)d_in[6];
    const float* b_hh  = (const float*)d_in[7];
    const float* W_out = (const float*)d_in[8];
    const float* b_out = (const float*)d_in[9];
    float* out = (float*)d_out;

    cudaFuncSetAttribute(lstm_persist_kernel,
                         cudaFuncAttributeMaxDynamicSharedMemorySize, SMEM_TOTAL_P);

    init_out_kernel<<<(B_SZ * T_STEPS + 255) / 256, 256>>>(out, b_out);
    conv_w_kernel<<<(G4 * H_SZ + 255) / 256, 256>>>(W_hh);
    conv_wih_kernel<<<(G4 * I_SZ + 255) / 256, 256>>>(W_ih, b_ih, b_hh);
    split_h0_kernel<<<(B_SZ * H_SZ + 255) / 256, 256>>>(h0);
    split_x_kernel<<<(int)(((size_t)MT * I_SZ + 255) / 256), 256>>>(obs, act);

    dim3 gxg(G4 / 128, MT / 64);
    xg_mma_kernel<<<gxg, 256>>>();

    dim3 gp(32, 4);
    lstm_persist_kernel<<<gp, 256, SMEM_TOTAL_P>>>(c0, W_out, out);
}